// round 12
// baseline (speedup 1.0000x reference)
#include <cuda_runtime.h>
#include <cuda_fp16.h>
#include <cstdint>

// Problem constants
#define NN 2048      // nodes
#define DD 16        // embedding dim
#define BB 64        // batch
#define CC 64        // in channels
#define OO 64        // out channels
#define KK 3         // cheb order
#define KC (KK*CC)   // 192
#define WCOLS (KC*OO) // 12288
#define BC (BB*CC)   // 4096 columns of the big GEMM

// ---------------- scratch (static device allocations allowed) ----------------
__device__ __half g_Ah  [(size_t)NN * NN];      // 8 MB : exp(relu(sim)-max) fp16 (UNNORMALIZED)
__device__ float  g_inv [NN];                   // per-row 1/sum for softmax
__device__ __half g_XTh [(size_t)BC * NN];      // 16 MB: XT[bc][m] = feat[b][m][c]
__device__ __half g_Y1Th[(size_t)BC * NN];      // 16 MB: Y1 transposed (gemm1 B)
__device__ __half g_Fnh [(size_t)NN * BB * CC]; // 16 MB: feat fp16 [N,B,C]
__device__ __half g_Y1nh[(size_t)NN * BB * CC]; // 16 MB: Y1  fp16 [N,B,C]
__device__ __half g_Y2nh[(size_t)NN * BB * CC]; // 16 MB: Y2  fp16 [N,B,C]
__device__ __half g_Wh  [(size_t)NN * WCOLS];   // 50 MB: per-node weights fp16
// dependency counters
__device__ int    g_c_bc0[32];   // gemm0 bc-stripe done (target 16)
__device__ int    g_c_s1 [16];   // gemm1 m-stripe done  (target 32)
__device__ int    g_c_cw [32];   // cw 64-node block done (target 96)

// ---------------- PTX helpers (baseline ISA only) ----------------
__device__ __forceinline__ uint32_t smem_u32(const void* p) {
    uint32_t a;
    asm("{ .reg .u64 t; cvta.to.shared.u64 t, %1; cvt.u32.u64 %0, t; }" : "=r"(a) : "l"(p));
    return a;
}
#define CP_ASYNC16(dst, src) \
    asm volatile("cp.async.cg.shared.global [%0], [%1], 16;" :: "r"(dst), "l"(src))
#define CP_COMMIT() asm volatile("cp.async.commit_group;" ::: "memory")
#define CP_WAIT2()  asm volatile("cp.async.wait_group 2;" ::: "memory")
#define CP_WAIT1()  asm volatile("cp.async.wait_group 1;" ::: "memory")
#define CP_WAIT0()  asm volatile("cp.async.wait_group 0;" ::: "memory")

__device__ __forceinline__ void ldsm4(uint32_t* r, uint32_t addr) {
    asm volatile("ldmatrix.sync.aligned.m8n8.x4.shared.b16 {%0,%1,%2,%3}, [%4];"
        : "=r"(r[0]), "=r"(r[1]), "=r"(r[2]), "=r"(r[3]) : "r"(addr));
}
__device__ __forceinline__ void ldsm4t(uint32_t* r, uint32_t addr) {
    asm volatile("ldmatrix.sync.aligned.m8n8.x4.trans.shared.b16 {%0,%1,%2,%3}, [%4];"
        : "=r"(r[0]), "=r"(r[1]), "=r"(r[2]), "=r"(r[3]) : "r"(addr));
}
__device__ __forceinline__ void mma16816(float* d, const uint32_t* a, const uint32_t* b) {
    asm volatile("mma.sync.aligned.m16n8k16.row.col.f32.f16.f16.f32 "
        "{%0,%1,%2,%3}, {%4,%5,%6,%7}, {%8,%9}, {%0,%1,%2,%3};"
        : "+f"(d[0]), "+f"(d[1]), "+f"(d[2]), "+f"(d[3])
        : "r"(a[0]), "r"(a[1]), "r"(a[2]), "r"(a[3]), "r"(b[0]), "r"(b[1]));
}
#define SWZ(o) ((o) ^ (((o) >> 3) & 0x70))

// ---------------------------------------------------------------------------
// Kernel 1 (fused prep): blocks [0,256)  -> adjacency exp (8 rows per block)
//                        blocks [256, 2304) -> feat transpose / fp16 convert
// ---------------------------------------------------------------------------
#define ADJ_TILE 256
#define ET_PITCH 258
#define ET_BYTES (DD * ET_PITCH * 4)          // 16512
#define PREP_SMEM (ET_BYTES + 8 * NN * 4)     // 82048

__global__ void __launch_bounds__(256) prep_kernel(
    const float* __restrict__ E, const float* __restrict__ feat)
{
    extern __shared__ char praw[];
    const int t = threadIdx.x;

    if (blockIdx.x < 256) {
        if (blockIdx.x == 0) {
            if (t < 32) { g_c_bc0[t] = 0; g_c_cw[t] = 0; }
            if (t < 16) { g_c_s1[t] = 0; }
        }

        float* etile = (float*)praw;                 // [16][258] transposed
        float* rows  = (float*)(praw + ET_BYTES);    // [8][2048]
        const int lane = t & 31;
        const int w    = t >> 5;
        const int n    = blockIdx.x * 8 + w;

        float e[DD];
#pragma unroll
        for (int d = 0; d < DD; d++) e[d] = E[n * DD + d];

        float* myrow = rows + w * NN;

        for (int mt = 0; mt < NN / ADJ_TILE; mt++) {
#pragma unroll
            for (int i = 0; i < 4; i++) {            // transposed tile load
                int idx = t + i * 256;
                int r   = idx >> 2;
                int c4  = (idx & 3) * 4;
                float4 v = *(const float4*)(E + (size_t)(mt * ADJ_TILE + r) * DD + c4);
                etile[(c4 + 0) * ET_PITCH + r] = v.x;
                etile[(c4 + 1) * ET_PITCH + r] = v.y;
                etile[(c4 + 2) * ET_PITCH + r] = v.z;
                etile[(c4 + 3) * ET_PITCH + r] = v.w;
            }
            __syncthreads();
#pragma unroll 2
            for (int j = 0; j < ADJ_TILE / 32; j++) {
                int mm = j * 32 + lane;
                float s = 0.f;
#pragma unroll
                for (int d = 0; d < DD; d++) s += e[d] * etile[d * ET_PITCH + mm];
                myrow[mt * ADJ_TILE + mm] = s;
            }
            __syncthreads();
        }

        float lmax = 0.0f;
#pragma unroll 4
        for (int m = lane; m < NN; m += 32) lmax = fmaxf(lmax, myrow[m]);
#pragma unroll
        for (int off = 16; off > 0; off >>= 1)
            lmax = fmaxf(lmax, __shfl_xor_sync(0xffffffffu, lmax, off));

        float lsum = 0.f;
#pragma unroll 4
        for (int m = lane; m < NN; m += 32) {
            float v = expf(fmaxf(myrow[m], 0.0f) - lmax);
            lsum += v;
            g_Ah[(size_t)n * NN + m] = __float2half(v);
        }
#pragma unroll
        for (int off = 16; off > 0; off >>= 1)
            lsum += __shfl_xor_sync(0xffffffffu, lsum, off);
        if (lane == 0) g_inv[n] = 1.0f / lsum;
    } else {
        const int bid2 = blockIdx.x - 256;
        const int m0 = (bid2 & 31) * 64;
        const int b  = bid2 >> 5;
        float (*tile)[65] = (float(*)[65])praw;

        const int mr = t >> 4, c4 = (t & 15) * 4;
#pragma unroll
        for (int p = 0; p < 4; p++) {
            const int m = m0 + mr + p * 16;
            float4 v = *(const float4*)(feat + ((size_t)b * NN + m) * CC + c4);
            tile[mr + p * 16][c4 + 0] = v.x;
            tile[mr + p * 16][c4 + 1] = v.y;
            tile[mr + p * 16][c4 + 2] = v.z;
            tile[mr + p * 16][c4 + 3] = v.w;
            __half2 h0 = __floats2half2_rn(v.x, v.y);
            __half2 h1 = __floats2half2_rn(v.z, v.w);
            *(uint2*)(g_Fnh + ((size_t)m * BB + b) * CC + c4) =
                make_uint2(*(uint32_t*)&h0, *(uint32_t*)&h1);
        }
        __syncthreads();

        const int cl = t >> 4, m4 = (t & 15) * 4;
#pragma unroll
        for (int p = 0; p < 4; p++) {
            int c = cl + p * 16;
            __half2 p0 = __floats2half2_rn(tile[m4 + 0][c], tile[m4 + 1][c]);
            __half2 p1 = __floats2half2_rn(tile[m4 + 2][c], tile[m4 + 3][c]);
            *(uint2*)(g_XTh + (size_t)(b * 64 + c) * NN + m0 + m4) =
                make_uint2(*(uint32_t*)&p0, *(uint32_t*)&p1);
        }
    }
}

// ---------------------------------------------------------------------------
// compute_weights as a 128-thread device block (in mega launch; no deps)
// ---------------------------------------------------------------------------
__device__ void cw_block(char* smem, const float* __restrict__ E,
                         const float* __restrict__ Wp, int cwid)
{
    const int col0 = (cwid % 96) * 128;
    const int n0   = (cwid / 96) * 64;
    const int t    = threadIdx.x;   // 0..127

    float* ws = (float*)smem;        // [16][128]
    float* es = ws + DD * 128;       // [64][16]

#pragma unroll
    for (int i = 0; i < 4; i++) {
        int idx = t + i * 128;
        int r = idx >> 5;
        int c = (idx & 31) * 4;
        *(float4*)&ws[r * 128 + c] = *(const float4*)(Wp + (size_t)r * WCOLS + col0 + c);
    }
#pragma unroll
    for (int i = 0; i < 2; i++) {
        int idx = t + i * 128;
        int r = idx >> 2;
        int c = (idx & 3) * 4;
        *(float4*)&es[r * DD + c] = *(const float4*)(E + (n0 + r) * DD + c);
    }
    __syncthreads();

    const int tx = t & 31;
    const int ty = t >> 5;
#pragma unroll
    for (int nn = ty; nn < 64; nn += 4) {
        float4 acc = make_float4(0.f, 0.f, 0.f, 0.f);
#pragma unroll
        for (int d = 0; d < DD; d++) {
            float ev = es[nn * DD + d];
            float4 w = *(const float4*)&ws[d * 128 + tx * 4];
            acc.x += ev * w.x; acc.y += ev * w.y;
            acc.z += ev * w.z; acc.w += ev * w.w;
        }
        __half2 h0 = __floats2half2_rn(acc.x, acc.y);
        __half2 h1 = __floats2half2_rn(acc.z, acc.w);
        *(uint2*)(g_Wh + (size_t)(n0 + nn) * WCOLS + col0 + tx * 4) =
            make_uint2(*(uint32_t*)&h0, *(uint32_t*)&h1);
    }
    __syncthreads();
    if (t == 0) {
        __threadfence();
        atomicAdd(&g_c_cw[cwid / 96], 1);
    }
}

// ---------------------------------------------------------------------------
// final_gconv as a 128-thread device block (in mega launch).
// Waits on gemm1 m-stripe AND cw n-block for its node.
// ---------------------------------------------------------------------------
#define FG_A_OFF   0
#define FG_B_OFF   24576
#define FG_BIAS    49152
#define FG_OPITCH  68

__device__ void final_block(char* sal, uint32_t sb, int n,
                            const float* __restrict__ E,
                            const float* __restrict__ biasP,
                            float* __restrict__ out)
{
    const int t    = threadIdx.x;   // 0..127
    const int lane = t & 31;
    const int wid  = t >> 5;
    const int wm   = wid >> 1;
    const int wn   = wid & 1;

    if (t == 0) {
        while (atomicAdd(&g_c_s1[n >> 7], 0) < 32) __nanosleep(64);
        while (atomicAdd(&g_c_cw[n >> 6], 0) < 96) __nanosleep(64);
        __threadfence();
    }
    __syncthreads();

    const char* asrc[KK] = {
        (const char*)(g_Fnh  + (size_t)n * (BB * CC)),
        (const char*)(g_Y1nh + (size_t)n * (BB * CC)),
        (const char*)(g_Y2nh + (size_t)n * (BB * CC)) };
    const char* wsrc = (const char*)(g_Wh + (size_t)n * WCOLS);
#pragma unroll
    for (int p = 0; p < 3; p++) {
#pragma unroll
        for (int i = 0; i < 4; i++) {
            int idx = t + i * 128;
            uint32_t so = SWZ((uint32_t)(idx * 16));
            CP_ASYNC16(sb + FG_A_OFF + p * 8192 + so, asrc[p] + idx * 16);
        }
#pragma unroll
        for (int i = 0; i < 4; i++) {
            int idx = p * 512 + t + i * 128;
            uint32_t so = SWZ((uint32_t)(idx * 16));
            CP_ASYNC16(sb + FG_B_OFF + so, wsrc + (size_t)idx * 16);
        }
        CP_COMMIT();
    }

    float* bias_s = (float*)(sal + FG_BIAS);
    if (t < OO) {
        float s = 0.f;
#pragma unroll
        for (int d = 0; d < DD; d++) s += E[n * DD + d] * biasP[d * OO + t];
        bias_s[t] = s;
    }

    float acc[2][4][4];
#pragma unroll
    for (int mf = 0; mf < 2; mf++)
#pragma unroll
        for (int nf = 0; nf < 4; nf++)
#pragma unroll
            for (int q = 0; q < 4; q++) acc[mf][nf][q] = 0.f;

    const int a_row  = lane & 15;
    const int a_kofs = (lane >> 4) << 4;
    const int bt_row = lane & 15;
    const int bt_col = (lane >> 4) << 3;

#pragma unroll
    for (int p = 0; p < 3; p++) {
        if (p == 0) { CP_WAIT2(); } else if (p == 1) { CP_WAIT1(); } else { CP_WAIT0(); }
        __syncthreads();
#pragma unroll
        for (int kko = 0; kko < 4; kko++) {
            const int kk = p * 4 + kko;
            uint32_t a[2][4], b[2][4];
#pragma unroll
            for (int mf = 0; mf < 2; mf++)
                ldsm4(a[mf], sb + FG_A_OFF + p * 8192 +
                      SWZ((uint32_t)((wm * 32 + mf * 16 + a_row) * 128 + kko * 32 + a_kofs)));
#pragma unroll
            for (int j = 0; j < 2; j++)
                ldsm4t(b[j], sb + FG_B_OFF +
                       SWZ((uint32_t)((kk * 16 + bt_row) * 128 + (wn * 32 + j * 16 + bt_col) * 2)));
#pragma unroll
            for (int mf = 0; mf < 2; mf++)
#pragma unroll
                for (int j = 0; j < 2; j++) {
                    mma16816(acc[mf][j * 2 + 0], a[mf], &b[j][0]);
                    mma16816(acc[mf][j * 2 + 1], a[mf], &b[j][2]);
                }
        }
    }
    __syncthreads();

    float* osm = (float*)sal;
#pragma unroll
    for (int mf = 0; mf < 2; mf++)
#pragma unroll
        for (int nf = 0; nf < 4; nf++) {
            int r = wm * 32 + mf * 16 + (lane >> 2);
            int c = wn * 32 + nf * 8 + (lane & 3) * 2;
            osm[r * FG_OPITCH + c]           = acc[mf][nf][0];
            osm[r * FG_OPITCH + c + 1]       = acc[mf][nf][1];
            osm[(r + 8) * FG_OPITCH + c]     = acc[mf][nf][2];
            osm[(r + 8) * FG_OPITCH + c + 1] = acc[mf][nf][3];
        }
    __syncthreads();

    const int b  = t >> 1;
    const int q0 = (t & 1) * 32;
    float* dst = out + ((size_t)b * NN + n) * OO + q0;
#pragma unroll
    for (int i = 0; i < 8; i++) {
        float4 v = *(float4*)&osm[b * FG_OPITCH + q0 + i * 4];
        v.x += bias_s[q0 + i * 4 + 0];
        v.y += bias_s[q0 + i * 4 + 1];
        v.z += bias_s[q0 + i * 4 + 2];
        v.w += bias_s[q0 + i * 4 + 3];
        *(float4*)(dst + i * 4) = v;
    }
}

// ---------------------------------------------------------------------------
// MEGA kernel (correct bid ordering: spinners LAST):
//   bid [0,512)     : gemm0  D = A @ XT   (bc-stripe-major; no waits)
//   bid [512,3584)  : cw_block            (no waits)
//   bid [3584,4096) : gemm1  D = A @ Y1T  (waits gemm0 bc-stripe)
//   bid [4096,6144) : final_block         (waits gemm1 m-stripe + cw)
// ---------------------------------------------------------------------------
#define MT 128
#define NT 128
#define KCH 64
#define NCH (NN / KCH)     // 32
#define ASTG (MT * 128)
#define BSTG (NT * 128)
#define STG_BYTES (ASTG + BSTG)
#define STAGES 3
#define EPI_PITCH 132
#define GEMM_SMEM (STAGES * STG_BYTES + 1024)
#define GEMM_CTAS 512
#define CW_CTAS   3072
#define MEGA_CTAS (GEMM_CTAS * 2 + CW_CTAS + NN)   // 6144

__global__ void __launch_bounds__(128, 2) mega_kernel(
    const float* __restrict__ feat,
    const float* __restrict__ E,
    const float* __restrict__ Wp,
    const float* __restrict__ biasP,
    float* __restrict__ out)
{
    extern __shared__ char smem_raw[];
    char* sal = (char*)(((uintptr_t)smem_raw + 1023) & ~(uintptr_t)1023);
    const uint32_t sb = smem_u32(sal);
    const int bid = blockIdx.x;
    const int t   = threadIdx.x;

    if (bid >= 512 && bid < 3584) { cw_block(smem_raw, E, Wp, bid - 512); return; }
    if (bid >= 4096) { final_block(sal, sb, bid - 4096, E, biasP, out); return; }

    const int pass = (bid >= 3584) ? 1 : 0;
    int m0, n0;
    if (pass == 0) { m0 = (bid & 15) * MT;      n0 = (bid >> 4) * NT; }
    else           { int j = bid - 3584; m0 = (j >> 5) * MT; n0 = (j & 31) * NT; }

    if (pass == 1) {   // wait for gemm0 bc-stripe n0 (dispatched after all cw)
        if (t == 0) {
            while (atomicAdd(&g_c_bc0[n0 >> 7], 0) < 16) __nanosleep(64);
            __threadfence();
        }
        __syncthreads();
    }

    const int lane = t & 31;
    const int wid  = t >> 5;
    const int wm   = wid >> 1;
    const int wn   = wid & 1;

    const __half* __restrict__ Bsrc = pass ? g_Y1Th : g_XTh;

    float acc[4][8][4];
#pragma unroll
    for (int i = 0; i < 4; i++)
#pragma unroll
        for (int j = 0; j < 8; j++)
#pragma unroll
            for (int q = 0; q < 4; q++) acc[i][j][q] = 0.f;

    auto load_chunk = [&](int ch, int s) {
        const uint32_t stA = sb + s * STG_BYTES;
        const uint32_t stB = stA + ASTG;
        const __half* agp = g_Ah + (size_t)m0 * NN + ch * KCH;
        const __half* bgp = Bsrc + (size_t)n0 * NN + ch * KCH;
#pragma unroll
        for (int i = 0; i < 8; i++) {
            int idx = t + i * 128;
            int r = idx >> 3, c = idx & 7;
            uint32_t so = SWZ((uint32_t)(r * 128 + c * 16));
            CP_ASYNC16(stA + so, agp + (size_t)r * NN + c * 8);
            CP_ASYNC16(stB + so, bgp + (size_t)r * NN + c * 8);
        }
        CP_COMMIT();
    };

    load_chunk(0, 0);
    load_chunk(1, 1);

    const int a_row  = (lane & 15);
    const int a_kofs = (lane >> 4) << 4;
    const int b_row  = ((lane >> 4) << 3) + (lane & 7);
    const int b_kofs = ((lane >> 3) & 1) << 4;

    for (int ch = 0; ch < NCH; ch++) {
        const int s = ch % STAGES;
        if (ch >= NCH - 2) { CP_WAIT0(); } else { CP_WAIT1(); }
        __syncthreads();
        if (ch + 2 < NCH) load_chunk(ch + 2, (ch + 2) % STAGES);

        const uint32_t stA = sb + s * STG_BYTES;
        const uint32_t stB = stA + ASTG;
#pragma unroll
        for (int kk = 0; kk < 4; kk++) {
            uint32_t a[4][4], b[4][4];
#pragma unroll
            for (int mf = 0; mf < 4; mf++) {
                int r = wm * 64 + mf * 16 + a_row;
                ldsm4(a[mf], stA + SWZ((uint32_t)(r * 128 + kk * 32 + a_kofs)));
            }
#pragma unroll
            for (int nf2 = 0; nf2 < 4; nf2++) {
                int r = wn * 64 + nf2 * 16 + b_row;
                ldsm4(b[nf2], stB + SWZ((uint32_t)(r * 128 + kk * 32 + b_kofs)));
            }
#pragma unroll
            for (int mf = 0; mf < 4; mf++)
#pragma unroll
                for (int nf = 0; nf < 8; nf++)
                    mma16816(acc[mf][nf], a[mf], &b[nf >> 1][(nf & 1) * 2]);
        }
    }
    __syncthreads();

    // ---- epilogue: stage accumulators through smem (fp32) ----
    float* esm = (float*)sal;
#pragma unroll
    for (int mf = 0; mf < 4; mf++) {
#pragma unroll
        for (int nf = 0; nf < 8; nf++) {
            int r = wm * 64 + mf * 16 + (lane >> 2);
            int c = wn * 64 + nf * 8 + (lane & 3) * 2;
            esm[r * EPI_PITCH + c]           = acc[mf][nf][0];
            esm[r * EPI_PITCH + c + 1]       = acc[mf][nf][1];
            esm[(r + 8) * EPI_PITCH + c]     = acc[mf][nf][2];
            esm[(r + 8) * EPI_PITCH + c + 1] = acc[mf][nf][3];
        }
    }
    __syncthreads();

    const int r = t;               // 0..127
    const int n = m0 + r;
    const float inv = g_inv[n];
    if (pass == 0) {
#pragma unroll
        for (int h = 0; h < 2; h++) {   // g_Y1nh fp16 [N,B,C]
            const int b = (n0 >> 6) + h;
            uint4* dst = (uint4*)(g_Y1nh + ((size_t)n * BB + b) * CC);
#pragma unroll
            for (int i = 0; i < 8; i++) {
                float4 v0 = *(float4*)&esm[r * EPI_PITCH + h * 64 + i * 8];
                float4 v1 = *(float4*)&esm[r * EPI_PITCH + h * 64 + i * 8 + 4];
                __half2 a0 = __floats2half2_rn(v0.x * inv, v0.y * inv);
                __half2 a1 = __floats2half2_rn(v0.z * inv, v0.w * inv);
                __half2 a2 = __floats2half2_rn(v1.x * inv, v1.y * inv);
                __half2 a3 = __floats2half2_rn(v1.z * inv, v1.w * inv);
                dst[i] = make_uint4(*(uint32_t*)&a0, *(uint32_t*)&a1,
                                    *(uint32_t*)&a2, *(uint32_t*)&a3);
            }
        }
        {   // g_Y1Th fp16 [bc][m]
            const int j = r;
            uint4* d4 = (uint4*)(g_Y1Th + (size_t)(n0 + j) * NN + m0);
#pragma unroll
            for (int q = 0; q < 16; q++) {
                uint32_t p[4];
#pragma unroll
                for (int u = 0; u < 4; u++) {
                    int rr = q * 8 + u * 2;
                    __half2 hv = __floats2half2_rn(
                        esm[rr * EPI_PITCH + j]       * g_inv[m0 + rr],
                        esm[(rr + 1) * EPI_PITCH + j] * g_inv[m0 + rr + 1]);
                    p[u] = *(uint32_t*)&hv;
                }
                d4[q] = make_uint4(p[0], p[1], p[2], p[3]);
            }
        }
        __syncthreads();
        if (t == 0) {
            __threadfence();
            atomicAdd(&g_c_bc0[(unsigned)n0 >> 7], 1);
        }
    } else {
#pragma unroll
        for (int h = 0; h < 2; h++) {
            const int b = (n0 >> 6) + h;
            const float4* fsrc = (const float4*)(feat + ((size_t)b * NN + n) * CC);
            uint4* dst = (uint4*)(g_Y2nh + ((size_t)n * BB + b) * CC);
            const float s2 = 2.f * inv;
#pragma unroll
            for (int i = 0; i < 8; i++) {
                float4 v0 = *(float4*)&esm[r * EPI_PITCH + h * 64 + i * 8];
                float4 v1 = *(float4*)&esm[r * EPI_PITCH + h * 64 + i * 8 + 4];
                float4 f0 = fsrc[i * 2], f1 = fsrc[i * 2 + 1];
                __half2 a0 = __floats2half2_rn(s2 * v0.x - f0.x, s2 * v0.y - f0.y);
                __half2 a1 = __floats2half2_rn(s2 * v0.z - f0.z, s2 * v0.w - f0.w);
                __half2 a2 = __floats2half2_rn(s2 * v1.x - f1.x, s2 * v1.y - f1.y);
                __half2 a3 = __floats2half2_rn(s2 * v1.z - f1.z, s2 * v1.w - f1.w);
                dst[i] = make_uint4(*(uint32_t*)&a0, *(uint32_t*)&a1,
                                    *(uint32_t*)&a2, *(uint32_t*)&a3);
            }
        }
        __syncthreads();
        if (t == 0) {
            __threadfence();
            atomicAdd(&g_c_s1[(unsigned)m0 >> 7], 1);
        }
    }
}

// ---------------------------------------------------------------------------
extern "C" void kernel_launch(void* const* d_in, const int* in_sizes, int n_in,
                              void* d_out, int out_size)
{
    const float* E     = (const float*)d_in[0];  // [2048,16]
    const float* feat  = (const float*)d_in[1];  // [64,2048,64]
    const float* Wp    = (const float*)d_in[2];  // [16,3,64,64]
    const float* biasP = (const float*)d_in[3];  // [16,64]
    float* out = (float*)d_out;                  // [64,2048,64]

    cudaFuncSetAttribute(prep_kernel, cudaFuncAttributeMaxDynamicSharedMemorySize, PREP_SMEM);
    cudaFuncSetAttribute(mega_kernel, cudaFuncAttributeMaxDynamicSharedMemorySize, GEMM_SMEM);

    prep_kernel<<<256 + 2048, 256, PREP_SMEM>>>(E, feat);
    mega_kernel<<<MEGA_CTAS, 128, GEMM_SMEM>>>(feat, E, Wp, biasP, out);
}

// round 13
// speedup vs baseline: 1.0412x; 1.0412x over previous
#include <cuda_runtime.h>
#include <cuda_fp16.h>
#include <cstdint>

// Problem constants
#define NN 2048      // nodes
#define DD 16        // embedding dim
#define BB 64        // batch
#define CC 64        // in channels
#define OO 64        // out channels
#define KK 3         // cheb order
#define KC (KK*CC)   // 192
#define WCOLS (KC*OO) // 12288
#define BC (BB*CC)   // 4096 columns of the big GEMM

// ---------------- scratch (static device allocations allowed) ----------------
__device__ __half g_Ah  [(size_t)NN * NN];      // 8 MB : exp(relu(sim)-max) fp16 (UNNORMALIZED)
__device__ float  g_inv [NN];                   // per-row 1/sum for softmax
__device__ __half g_XTh [(size_t)BC * NN];      // 16 MB: XT[bc][m] = feat[b][m][c]
__device__ __half g_Y1Th[(size_t)BC * NN];      // 16 MB: Y1 transposed (pass-1 B)
__device__ __half g_Fnh [(size_t)NN * BB * CC]; // 16 MB: feat fp16 [N,B,C]
__device__ __half g_Y1nh[(size_t)NN * BB * CC]; // 16 MB: Y1  fp16 [N,B,C]
__device__ __half g_Y2nh[(size_t)NN * BB * CC]; // 16 MB: Y2  fp16 [N,B,C]
__device__ __half g_Wh  [(size_t)NN * WCOLS];   // 50 MB: per-node weights fp16
__device__ int    g_stripe_cnt[16];             // gemm<1> m-stripe completion

// ---------------- PTX helpers (baseline ISA only) ----------------
__device__ __forceinline__ uint32_t smem_u32(const void* p) {
    uint32_t a;
    asm("{ .reg .u64 t; cvta.to.shared.u64 t, %1; cvt.u32.u64 %0, t; }" : "=r"(a) : "l"(p));
    return a;
}
#define CP_ASYNC16(dst, src) \
    asm volatile("cp.async.cg.shared.global [%0], [%1], 16;" :: "r"(dst), "l"(src))
#define CP_COMMIT() asm volatile("cp.async.commit_group;" ::: "memory")
#define CP_WAIT2()  asm volatile("cp.async.wait_group 2;" ::: "memory")
#define CP_WAIT1()  asm volatile("cp.async.wait_group 1;" ::: "memory")
#define CP_WAIT0()  asm volatile("cp.async.wait_group 0;" ::: "memory")

__device__ __forceinline__ void ldsm4(uint32_t* r, uint32_t addr) {
    asm volatile("ldmatrix.sync.aligned.m8n8.x4.shared.b16 {%0,%1,%2,%3}, [%4];"
        : "=r"(r[0]), "=r"(r[1]), "=r"(r[2]), "=r"(r[3]) : "r"(addr));
}
__device__ __forceinline__ void ldsm4t(uint32_t* r, uint32_t addr) {
    asm volatile("ldmatrix.sync.aligned.m8n8.x4.trans.shared.b16 {%0,%1,%2,%3}, [%4];"
        : "=r"(r[0]), "=r"(r[1]), "=r"(r[2]), "=r"(r[3]) : "r"(addr));
}
__device__ __forceinline__ void mma16816(float* d, const uint32_t* a, const uint32_t* b) {
    asm volatile("mma.sync.aligned.m16n8k16.row.col.f32.f16.f16.f32 "
        "{%0,%1,%2,%3}, {%4,%5,%6,%7}, {%8,%9}, {%0,%1,%2,%3};"
        : "+f"(d[0]), "+f"(d[1]), "+f"(d[2]), "+f"(d[3])
        : "r"(a[0]), "r"(a[1]), "r"(a[2]), "r"(a[3]), "r"(b[0]), "r"(b[1]));
}
#define SWZ(o) ((o) ^ (((o) >> 3) & 0x70))

// ---------------------------------------------------------------------------
// Kernel 1 (fused prep), 128-thread blocks for 4 CTAs/SM:
//   blocks [0,512)     -> adjacency exp (4 rows per block, 1 warp per row)
//   blocks [512, 2560) -> feat transpose / fp16 convert
// Adjacency: single pass of dots into smem row buffer; E-tile TRANSPOSED
// [d][m] pitch 258 (conflict-free). Stores UNNORMALIZED exp(s - rowmax) fp16
// + g_inv[n]; GEMM epilogue applies inv.
// ---------------------------------------------------------------------------
#define ADJ_TILE 256
#define ET_PITCH 258
#define ET_BYTES (DD * ET_PITCH * 4)          // 16512
#define PREP_SMEM (ET_BYTES + 4 * NN * 4)     // 16512 + 32768 = 49280

__global__ void __launch_bounds__(128) prep_kernel(
    const float* __restrict__ E, const float* __restrict__ feat)
{
    extern __shared__ char praw[];
    const int t = threadIdx.x;

    if (blockIdx.x < 512) {
        if (blockIdx.x == 0 && t < 16) g_stripe_cnt[t] = 0;

        float* etile = (float*)praw;                 // [16][258] transposed
        float* rows  = (float*)(praw + ET_BYTES);    // [4][2048]
        const int lane = t & 31;
        const int w    = t >> 5;                     // 0..3
        const int n    = blockIdx.x * 4 + w;

        float e[DD];
#pragma unroll
        for (int d = 0; d < DD; d++) e[d] = E[n * DD + d];

        float* myrow = rows + w * NN;

        // ---- single pass: dots into row buffer ----
        for (int mt = 0; mt < NN / ADJ_TILE; mt++) {
#pragma unroll
            for (int i = 0; i < 8; i++) {            // transposed tile load
                int idx = t + i * 128;               // 0..1023 float4s
                int r   = idx >> 2;
                int c4  = (idx & 3) * 4;
                float4 v = *(const float4*)(E + (size_t)(mt * ADJ_TILE + r) * DD + c4);
                etile[(c4 + 0) * ET_PITCH + r] = v.x;
                etile[(c4 + 1) * ET_PITCH + r] = v.y;
                etile[(c4 + 2) * ET_PITCH + r] = v.z;
                etile[(c4 + 3) * ET_PITCH + r] = v.w;
            }
            __syncthreads();
#pragma unroll 2
            for (int j = 0; j < ADJ_TILE / 32; j++) {
                int mm = j * 32 + lane;
                float s = 0.f;
#pragma unroll
                for (int d = 0; d < DD; d++) s += e[d] * etile[d * ET_PITCH + mm];
                myrow[mt * ADJ_TILE + mm] = s;       // raw s (relu folded into max)
            }
            __syncthreads();
        }

        // ---- row max (relu implied: lmax starts at 0) ----
        float lmax = 0.0f;
#pragma unroll 4
        for (int m = lane; m < NN; m += 32) lmax = fmaxf(lmax, myrow[m]);
#pragma unroll
        for (int off = 16; off > 0; off >>= 1)
            lmax = fmaxf(lmax, __shfl_xor_sync(0xffffffffu, lmax, off));

        // ---- exp + sum + store unnormalized fp16 ----
        float lsum = 0.f;
#pragma unroll 4
        for (int m = lane; m < NN; m += 32) {
            float v = expf(fmaxf(myrow[m], 0.0f) - lmax);
            lsum += v;
            g_Ah[(size_t)n * NN + m] = __float2half(v);
        }
#pragma unroll
        for (int off = 16; off > 0; off >>= 1)
            lsum += __shfl_xor_sync(0xffffffffu, lsum, off);
        if (lane == 0) g_inv[n] = 1.0f / lsum;
    } else {
        // ----- feat transpose + fp16 convert (writes XTh and Fnh [N,B,C]) -----
        const int bid2 = blockIdx.x - 512;
        const int m0 = (bid2 & 31) * 64;
        const int b  = bid2 >> 5;
        float (*tile)[65] = (float(*)[65])praw;

        const int mr = t >> 4, c4 = (t & 15) * 4;    // 8 rows per pass
#pragma unroll
        for (int p = 0; p < 8; p++) {
            const int m = m0 + mr + p * 8;
            float4 v = *(const float4*)(feat + ((size_t)b * NN + m) * CC + c4);
            tile[mr + p * 8][c4 + 0] = v.x;
            tile[mr + p * 8][c4 + 1] = v.y;
            tile[mr + p * 8][c4 + 2] = v.z;
            tile[mr + p * 8][c4 + 3] = v.w;
            __half2 h0 = __floats2half2_rn(v.x, v.y);
            __half2 h1 = __floats2half2_rn(v.z, v.w);
            *(uint2*)(g_Fnh + ((size_t)m * BB + b) * CC + c4) =
                make_uint2(*(uint32_t*)&h0, *(uint32_t*)&h1);
        }
        __syncthreads();

        const int cl = t >> 4, m4 = (t & 15) * 4;    // 8 cols per pass
#pragma unroll
        for (int p = 0; p < 8; p++) {
            int c = cl + p * 8;
            __half2 p0 = __floats2half2_rn(tile[m4 + 0][c], tile[m4 + 1][c]);
            __half2 p1 = __floats2half2_rn(tile[m4 + 2][c], tile[m4 + 3][c]);
            *(uint2*)(g_XTh + (size_t)(b * 64 + c) * NN + m0 + m4) =
                make_uint2(*(uint32_t*)&p0, *(uint32_t*)&p1);
        }
    }
}

// ---------------------------------------------------------------------------
// compute_weights as a 128-thread device block (folded into gemm<0> launch)
// ---------------------------------------------------------------------------
__device__ void cw_block(char* smem, const float* __restrict__ E,
                         const float* __restrict__ Wp, int cwid)
{
    const int col0 = (cwid % 96) * 128;
    const int n0   = (cwid / 96) * 64;
    const int t    = threadIdx.x;   // 0..127

    float* ws = (float*)smem;        // [16][128]
    float* es = ws + DD * 128;       // [64][16]

#pragma unroll
    for (int i = 0; i < 4; i++) {
        int idx = t + i * 128;
        int r = idx >> 5;
        int c = (idx & 31) * 4;
        *(float4*)&ws[r * 128 + c] = *(const float4*)(Wp + (size_t)r * WCOLS + col0 + c);
    }
#pragma unroll
    for (int i = 0; i < 2; i++) {
        int idx = t + i * 128;
        int r = idx >> 2;
        int c = (idx & 3) * 4;
        *(float4*)&es[r * DD + c] = *(const float4*)(E + (n0 + r) * DD + c);
    }
    __syncthreads();

    const int tx = t & 31;
    const int ty = t >> 5;
#pragma unroll
    for (int nn = ty; nn < 64; nn += 4) {
        float4 acc = make_float4(0.f, 0.f, 0.f, 0.f);
#pragma unroll
        for (int d = 0; d < DD; d++) {
            float ev = es[nn * DD + d];
            float4 w = *(const float4*)&ws[d * 128 + tx * 4];
            acc.x += ev * w.x; acc.y += ev * w.y;
            acc.z += ev * w.z; acc.w += ev * w.w;
        }
        __half2 h0 = __floats2half2_rn(acc.x, acc.y);
        __half2 h1 = __floats2half2_rn(acc.z, acc.w);
        *(uint2*)(g_Wh + (size_t)(n0 + nn) * WCOLS + col0 + tx * 4) =
            make_uint2(*(uint32_t*)&h0, *(uint32_t*)&h1);
    }
}

// ---------------------------------------------------------------------------
// final_gconv as a 128-thread device block (folded into gemm<1> launch).
// Waits on gemm1 m-stripe for its node (cw completed in launch 2).
// ---------------------------------------------------------------------------
#define FG_A_OFF   0       // 3 * 8192 = 24576
#define FG_B_OFF   24576   // 192 * 128 = 24576
#define FG_BIAS    49152   // 64 floats
#define FG_OPITCH  68

__device__ void final_block(char* sal, uint32_t sb, int n,
                            const float* __restrict__ E,
                            const float* __restrict__ biasP,
                            float* __restrict__ out)
{
    const int t    = threadIdx.x;   // 0..127
    const int lane = t & 31;
    const int wid  = t >> 5;
    const int wm   = wid >> 1;      // 0..1 : b rows wm*32
    const int wn   = wid & 1;       // 0..1 : o cols wn*32

    if (t == 0) {
        while (atomicAdd(&g_stripe_cnt[n >> 7], 0) < 32) __nanosleep(64);
        __threadfence();
    }
    __syncthreads();

    const char* asrc[KK] = {
        (const char*)(g_Fnh  + (size_t)n * (BB * CC)),
        (const char*)(g_Y1nh + (size_t)n * (BB * CC)),
        (const char*)(g_Y2nh + (size_t)n * (BB * CC)) };
    const char* wsrc = (const char*)(g_Wh + (size_t)n * WCOLS);
#pragma unroll
    for (int p = 0; p < 3; p++) {
#pragma unroll
        for (int i = 0; i < 4; i++) {
            int idx = t + i * 128;
            uint32_t so = SWZ((uint32_t)(idx * 16));
            CP_ASYNC16(sb + FG_A_OFF + p * 8192 + so, asrc[p] + idx * 16);
        }
#pragma unroll
        for (int i = 0; i < 4; i++) {
            int idx = p * 512 + t + i * 128;
            uint32_t so = SWZ((uint32_t)(idx * 16));
            CP_ASYNC16(sb + FG_B_OFF + so, wsrc + (size_t)idx * 16);
        }
        CP_COMMIT();
    }

    float* bias_s = (float*)(sal + FG_BIAS);
    if (t < OO) {
        float s = 0.f;
#pragma unroll
        for (int d = 0; d < DD; d++) s += E[n * DD + d] * biasP[d * OO + t];
        bias_s[t] = s;
    }

    float acc[2][4][4];
#pragma unroll
    for (int mf = 0; mf < 2; mf++)
#pragma unroll
        for (int nf = 0; nf < 4; nf++)
#pragma unroll
            for (int q = 0; q < 4; q++) acc[mf][nf][q] = 0.f;

    const int a_row  = lane & 15;
    const int a_kofs = (lane >> 4) << 4;
    const int bt_row = lane & 15;
    const int bt_col = (lane >> 4) << 3;

#pragma unroll
    for (int p = 0; p < 3; p++) {
        if (p == 0) { CP_WAIT2(); } else if (p == 1) { CP_WAIT1(); } else { CP_WAIT0(); }
        __syncthreads();
#pragma unroll
        for (int kko = 0; kko < 4; kko++) {
            const int kk = p * 4 + kko;
            uint32_t a[2][4], b[2][4];
#pragma unroll
            for (int mf = 0; mf < 2; mf++)
                ldsm4(a[mf], sb + FG_A_OFF + p * 8192 +
                      SWZ((uint32_t)((wm * 32 + mf * 16 + a_row) * 128 + kko * 32 + a_kofs)));
#pragma unroll
            for (int j = 0; j < 2; j++)
                ldsm4t(b[j], sb + FG_B_OFF +
                       SWZ((uint32_t)((kk * 16 + bt_row) * 128 + (wn * 32 + j * 16 + bt_col) * 2)));
#pragma unroll
            for (int mf = 0; mf < 2; mf++)
#pragma unroll
                for (int j = 0; j < 2; j++) {
                    mma16816(acc[mf][j * 2 + 0], a[mf], &b[j][0]);
                    mma16816(acc[mf][j * 2 + 1], a[mf], &b[j][2]);
                }
        }
    }
    __syncthreads();

    float* osm = (float*)sal;
#pragma unroll
    for (int mf = 0; mf < 2; mf++)
#pragma unroll
        for (int nf = 0; nf < 4; nf++) {
            int r = wm * 32 + mf * 16 + (lane >> 2);
            int c = wn * 32 + nf * 8 + (lane & 3) * 2;
            osm[r * FG_OPITCH + c]           = acc[mf][nf][0];
            osm[r * FG_OPITCH + c + 1]       = acc[mf][nf][1];
            osm[(r + 8) * FG_OPITCH + c]     = acc[mf][nf][2];
            osm[(r + 8) * FG_OPITCH + c + 1] = acc[mf][nf][3];
        }
    __syncthreads();

    const int b  = t >> 1;
    const int q0 = (t & 1) * 32;
    float* dst = out + ((size_t)b * NN + n) * OO + q0;
#pragma unroll
    for (int i = 0; i < 8; i++) {
        float4 v = *(float4*)&osm[b * FG_OPITCH + q0 + i * 4];
        v.x += bias_s[q0 + i * 4 + 0];
        v.y += bias_s[q0 + i * 4 + 1];
        v.z += bias_s[q0 + i * 4 + 2];
        v.w += bias_s[q0 + i * 4 + 3];
        *(float4*)(dst + i * 4) = v;
    }
}

// ---------------------------------------------------------------------------
// Kernel 2: mma.sync fp16 GEMM.  D[n, bc] = inv[n] * sum_m Ah[n,m] * B[bc, m]
//   PASS 0: B = g_XTh ; writes g_Y1nh + g_Y1Th.  bid >= 512 -> cw_block.
//   PASS 1: B = g_Y1Th; writes g_Y2nh; stripe counters; bid >= 512 -> final.
// ---------------------------------------------------------------------------
#define MT 128
#define NT 128
#define KCH 64
#define NCH (NN / KCH)     // 32
#define ASTG (MT * 128)    // 16 KB
#define BSTG (NT * 128)    // 16 KB
#define STG_BYTES (ASTG + BSTG)
#define STAGES 3
#define EPI_PITCH 132
#define GEMM_SMEM (STAGES * STG_BYTES + 1024)
#define GEMM_CTAS ((NN / MT) * (BC / NT))     // 512
#define CW_CTAS   ((WCOLS / 128) * (NN / 64)) // 3072

template <int PASS>
__global__ void __launch_bounds__(128, 2) gemm_mma(
    const float* __restrict__ feat,
    const float* __restrict__ E,
    const float* __restrict__ Wp,
    const float* __restrict__ biasP,
    float* __restrict__ out)
{
    extern __shared__ char smem_raw[];
    char* sal = (char*)(((uintptr_t)smem_raw + 1023) & ~(uintptr_t)1023);
    const uint32_t sb = smem_u32(sal);

    if (PASS == 0 && blockIdx.x >= GEMM_CTAS) {
        cw_block(smem_raw, E, Wp, blockIdx.x - GEMM_CTAS);
        return;
    }
    if (PASS == 1 && blockIdx.x >= GEMM_CTAS) {
        final_block(sal, sb, blockIdx.x - GEMM_CTAS, E, biasP, out);
        return;
    }

    const int t    = threadIdx.x;
    const int lane = t & 31;
    const int wid  = t >> 5;
    const int wm   = wid >> 1;
    const int wn   = wid & 1;
    const int m0   = PASS ? (blockIdx.x >> 5) * MT : (blockIdx.x & 15) * MT;
    const int n0   = PASS ? (blockIdx.x & 31) * NT : (blockIdx.x >> 4) * NT;

    const __half* __restrict__ Bsrc = PASS ? g_Y1Th : g_XTh;

    float acc[4][8][4];
#pragma unroll
    for (int i = 0; i < 4; i++)
#pragma unroll
        for (int j = 0; j < 8; j++)
#pragma unroll
            for (int q = 0; q < 4; q++) acc[i][j][q] = 0.f;

    auto load_chunk = [&](int ch, int s) {
        const uint32_t stA = sb + s * STG_BYTES;
        const uint32_t stB = stA + ASTG;
        const __half* agp = g_Ah + (size_t)m0 * NN + ch * KCH;
        const __half* bgp = Bsrc + (size_t)n0 * NN + ch * KCH;
#pragma unroll
        for (int i = 0; i < 8; i++) {
            int idx = t + i * 128;
            int r = idx >> 3, c = idx & 7;
            uint32_t so = SWZ((uint32_t)(r * 128 + c * 16));
            CP_ASYNC16(stA + so, agp + (size_t)r * NN + c * 8);
            CP_ASYNC16(stB + so, bgp + (size_t)r * NN + c * 8);
        }
        CP_COMMIT();
    };

    load_chunk(0, 0);
    load_chunk(1, 1);

    const int a_row  = (lane & 15);
    const int a_kofs = (lane >> 4) << 4;
    const int b_row  = ((lane >> 4) << 3) + (lane & 7);
    const int b_kofs = ((lane >> 3) & 1) << 4;

    for (int ch = 0; ch < NCH; ch++) {
        const int s = ch % STAGES;
        if (ch >= NCH - 2) { CP_WAIT0(); } else { CP_WAIT1(); }
        __syncthreads();
        if (ch + 2 < NCH) load_chunk(ch + 2, (ch + 2) % STAGES);

        const uint32_t stA = sb + s * STG_BYTES;
        const uint32_t stB = stA + ASTG;
#pragma unroll
        for (int kk = 0; kk < 4; kk++) {
            uint32_t a[4][4], b[4][4];
#pragma unroll
            for (int mf = 0; mf < 4; mf++) {
                int r = wm * 64 + mf * 16 + a_row;
                ldsm4(a[mf], stA + SWZ((uint32_t)(r * 128 + kk * 32 + a_kofs)));
            }
#pragma unroll
            for (int nf2 = 0; nf2 < 4; nf2++) {
                int r = wn * 64 + nf2 * 16 + b_row;
                ldsm4(b[nf2], stB + SWZ((uint32_t)(r * 128 + kk * 32 + b_kofs)));
            }
#pragma unroll
            for (int mf = 0; mf < 4; mf++)
#pragma unroll
                for (int nf = 0; nf < 8; nf++)
                    mma16816(acc[mf][nf], a[mf], &b[nf >> 1][(nf & 1) * 2]);
        }
    }
    __syncthreads();

    // ---- epilogue: stage accumulators through smem (fp32) ----
    float* esm = (float*)sal;
#pragma unroll
    for (int mf = 0; mf < 4; mf++) {
#pragma unroll
        for (int nf = 0; nf < 8; nf++) {
            int r = wm * 64 + mf * 16 + (lane >> 2);
            int c = wn * 64 + nf * 8 + (lane & 3) * 2;
            esm[r * EPI_PITCH + c]           = acc[mf][nf][0];
            esm[r * EPI_PITCH + c + 1]       = acc[mf][nf][1];
            esm[(r + 8) * EPI_PITCH + c]     = acc[mf][nf][2];
            esm[(r + 8) * EPI_PITCH + c + 1] = acc[mf][nf][3];
        }
    }
    __syncthreads();

    const int r = t;               // 0..127
    const int n = m0 + r;
    const float inv = g_inv[n];    // softmax row normalization (folded)
    if (PASS == 0) {
#pragma unroll
        for (int h = 0; h < 2; h++) {   // g_Y1nh fp16 [N,B,C]
            const int b = (n0 >> 6) + h;
            uint4* dst = (uint4*)(g_Y1nh + ((size_t)n * BB + b) * CC);
#pragma unroll
            for (int i = 0; i < 8; i++) {
                float4 v0 = *(float4*)&esm[r * EPI_PITCH + h * 64 + i * 8];
                float4 v1 = *(float4*)&esm[r * EPI_PITCH + h * 64 + i * 8 + 4];
                __half2 a0 = __floats2half2_rn(v0.x * inv, v0.y * inv);
                __half2 a1 = __floats2half2_rn(v0.z * inv, v0.w * inv);
                __half2 a2 = __floats2half2_rn(v1.x * inv, v1.y * inv);
                __half2 a3 = __floats2half2_rn(v1.z * inv, v1.w * inv);
                dst[i] = make_uint4(*(uint32_t*)&a0, *(uint32_t*)&a1,
                                    *(uint32_t*)&a2, *(uint32_t*)&a3);
            }
        }
        {   // g_Y1Th fp16 [bc][m]
            const int j = r;
            uint4* d4 = (uint4*)(g_Y1Th + (size_t)(n0 + j) * NN + m0);
#pragma unroll
            for (int q = 0; q < 16; q++) {
                uint32_t p[4];
#pragma unroll
                for (int u = 0; u < 4; u++) {
                    int rr = q * 8 + u * 2;
                    __half2 hv = __floats2half2_rn(
                        esm[rr * EPI_PITCH + j]       * g_inv[m0 + rr],
                        esm[(rr + 1) * EPI_PITCH + j] * g_inv[m0 + rr + 1]);
                    p[u] = *(uint32_t*)&hv;
                }
                d4[q] = make_uint4(p[0], p[1], p[2], p[3]);
            }
        }
    } else {
#pragma unroll
        for (int h = 0; h < 2; h++) {
            const int b = (n0 >> 6) + h;
            const float4* fsrc = (const float4*)(feat + ((size_t)b * NN + n) * CC);
            uint4* dst = (uint4*)(g_Y2nh + ((size_t)n * BB + b) * CC);
            const float s2 = 2.f * inv;
#pragma unroll
            for (int i = 0; i < 8; i++) {
                float4 v0 = *(float4*)&esm[r * EPI_PITCH + h * 64 + i * 8];
                float4 v1 = *(float4*)&esm[r * EPI_PITCH + h * 64 + i * 8 + 4];
                float4 f0 = fsrc[i * 2], f1 = fsrc[i * 2 + 1];
                __half2 a0 = __floats2half2_rn(s2 * v0.x - f0.x, s2 * v0.y - f0.y);
                __half2 a1 = __floats2half2_rn(s2 * v0.z - f0.z, s2 * v0.w - f0.w);
                __half2 a2 = __floats2half2_rn(s2 * v1.x - f1.x, s2 * v1.y - f1.y);
                __half2 a3 = __floats2half2_rn(s2 * v1.z - f1.z, s2 * v1.w - f1.w);
                dst[i] = make_uint4(*(uint32_t*)&a0, *(uint32_t*)&a1,
                                    *(uint32_t*)&a2, *(uint32_t*)&a3);
            }
        }
        __syncthreads();
        if (t == 0) {
            __threadfence();
            atomicAdd(&g_stripe_cnt[(unsigned)m0 >> 7], 1);
        }
    }
}

// ---------------------------------------------------------------------------
extern "C" void kernel_launch(void* const* d_in, const int* in_sizes, int n_in,
                              void* d_out, int out_size)
{
    const float* E     = (const float*)d_in[0];  // [2048,16]
    const float* feat  = (const float*)d_in[1];  // [64,2048,64]
    const float* Wp    = (const float*)d_in[2];  // [16,3,64,64]
    const float* biasP = (const float*)d_in[3];  // [16,64]
    float* out = (float*)d_out;                  // [64,2048,64]

    cudaFuncSetAttribute(prep_kernel, cudaFuncAttributeMaxDynamicSharedMemorySize, PREP_SMEM);
    cudaFuncSetAttribute(gemm_mma<0>, cudaFuncAttributeMaxDynamicSharedMemorySize, GEMM_SMEM);
    cudaFuncSetAttribute(gemm_mma<1>, cudaFuncAttributeMaxDynamicSharedMemorySize, GEMM_SMEM);

    prep_kernel<<<512 + 2048, 128, PREP_SMEM>>>(E, feat);
    gemm_mma<0><<<GEMM_CTAS + CW_CTAS, 128, GEMM_SMEM>>>(feat, E, Wp, biasP, out);
    gemm_mma<1><<<GEMM_CTAS + NN, 128, GEMM_SMEM>>>(feat, E, Wp, biasP, out);
}

// round 14
// speedup vs baseline: 1.0492x; 1.0077x over previous
#include <cuda_runtime.h>
#include <cuda_fp16.h>
#include <cstdint>

// Problem constants
#define NN 2048      // nodes
#define DD 16        // embedding dim
#define BB 64        // batch
#define CC 64        // in channels
#define OO 64        // out channels
#define KK 3         // cheb order
#define KC (KK*CC)   // 192
#define WCOLS (KC*OO) // 12288
#define BC (BB*CC)   // 4096 columns of the big GEMM

// ---------------- scratch (static device allocations allowed) ----------------
__device__ __half g_Ah  [(size_t)NN * NN];      // 8 MB : exp(relu(sim)-max) fp16 (UNNORMALIZED)
__device__ float  g_inv [NN];                   // per-row 1/sum for softmax
__device__ __half g_XTh [(size_t)BC * NN];      // 16 MB: XT[bc][m] = feat[b][m][c]
__device__ __half g_Y1Th[(size_t)BC * NN];      // 16 MB: Y1 transposed (pass-1 B)
__device__ __half g_Fnh [(size_t)NN * BB * CC]; // 16 MB: feat fp16 [N,B,C]
__device__ __half g_Y1nh[(size_t)NN * BB * CC]; // 16 MB: Y1  fp16 [N,B,C]
__device__ __half g_Y2nh[(size_t)NN * BB * CC]; // 16 MB: Y2  fp16 [N,B,C]
__device__ __half g_Wh  [(size_t)NN * WCOLS];   // 50 MB: per-node weights fp16
__device__ int    g_stripe_cnt[16];             // gemm<1> m-stripe completion

// ---------------- PTX helpers (baseline ISA only) ----------------
__device__ __forceinline__ uint32_t smem_u32(const void* p) {
    uint32_t a;
    asm("{ .reg .u64 t; cvta.to.shared.u64 t, %1; cvt.u32.u64 %0, t; }" : "=r"(a) : "l"(p));
    return a;
}
#define CP_ASYNC16(dst, src) \
    asm volatile("cp.async.cg.shared.global [%0], [%1], 16;" :: "r"(dst), "l"(src))
#define CP_COMMIT() asm volatile("cp.async.commit_group;" ::: "memory")
#define CP_WAIT2()  asm volatile("cp.async.wait_group 2;" ::: "memory")
#define CP_WAIT1()  asm volatile("cp.async.wait_group 1;" ::: "memory")
#define CP_WAIT0()  asm volatile("cp.async.wait_group 0;" ::: "memory")

__device__ __forceinline__ void ldsm4(uint32_t* r, uint32_t addr) {
    asm volatile("ldmatrix.sync.aligned.m8n8.x4.shared.b16 {%0,%1,%2,%3}, [%4];"
        : "=r"(r[0]), "=r"(r[1]), "=r"(r[2]), "=r"(r[3]) : "r"(addr));
}
__device__ __forceinline__ void ldsm4t(uint32_t* r, uint32_t addr) {
    asm volatile("ldmatrix.sync.aligned.m8n8.x4.trans.shared.b16 {%0,%1,%2,%3}, [%4];"
        : "=r"(r[0]), "=r"(r[1]), "=r"(r[2]), "=r"(r[3]) : "r"(addr));
}
__device__ __forceinline__ void mma16816(float* d, const uint32_t* a, const uint32_t* b) {
    asm volatile("mma.sync.aligned.m16n8k16.row.col.f32.f16.f16.f32 "
        "{%0,%1,%2,%3}, {%4,%5,%6,%7}, {%8,%9}, {%0,%1,%2,%3};"
        : "+f"(d[0]), "+f"(d[1]), "+f"(d[2]), "+f"(d[3])
        : "r"(a[0]), "r"(a[1]), "r"(a[2]), "r"(a[3]), "r"(b[0]), "r"(b[1]));
}
#define SWZ(o) ((o) ^ (((o) >> 3) & 0x70))

// ---------------------------------------------------------------------------
// Kernel 1 (fused prep): blocks [0,256)  -> adjacency exp (8 rows per block)
//                        blocks [256, 2304) -> feat transpose / fp16 convert
// Adjacency: SINGLE pass of dot products into a smem row buffer; E-tile held
// TRANSPOSED [d][m] pitch 258 (conflict-free). Stores UNNORMALIZED
// exp(s - rowmax) fp16 + g_inv[n]; GEMM epilogue applies inv.
// ---------------------------------------------------------------------------
#define ADJ_TILE 256
#define ET_PITCH 258
#define ET_BYTES (DD * ET_PITCH * 4)          // 16512
#define PREP_SMEM (ET_BYTES + 8 * NN * 4)     // 16512 + 65536 = 82048

__global__ void __launch_bounds__(256) prep_kernel(
    const float* __restrict__ E, const float* __restrict__ feat)
{
    extern __shared__ char praw[];
    const int t = threadIdx.x;

    if (blockIdx.x < 256) {
        if (blockIdx.x == 0 && t < 16) g_stripe_cnt[t] = 0;

        float* etile = (float*)praw;                 // [16][258] transposed
        float* rows  = (float*)(praw + ET_BYTES);    // [8][2048]
        const int lane = t & 31;
        const int w    = t >> 5;
        const int n    = blockIdx.x * 8 + w;

        float e[DD];
#pragma unroll
        for (int d = 0; d < DD; d++) e[d] = E[n * DD + d];

        float* myrow = rows + w * NN;

        // ---- single pass: dots into row buffer ----
        for (int mt = 0; mt < NN / ADJ_TILE; mt++) {
#pragma unroll
            for (int i = 0; i < 4; i++) {            // transposed tile load
                int idx = t + i * 256;               // 0..1023 float4s
                int r   = idx >> 2;
                int c4  = (idx & 3) * 4;
                float4 v = *(const float4*)(E + (size_t)(mt * ADJ_TILE + r) * DD + c4);
                etile[(c4 + 0) * ET_PITCH + r] = v.x;
                etile[(c4 + 1) * ET_PITCH + r] = v.y;
                etile[(c4 + 2) * ET_PITCH + r] = v.z;
                etile[(c4 + 3) * ET_PITCH + r] = v.w;
            }
            __syncthreads();
#pragma unroll 2
            for (int j = 0; j < ADJ_TILE / 32; j++) {
                int mm = j * 32 + lane;
                float s = 0.f;
#pragma unroll
                for (int d = 0; d < DD; d++) s += e[d] * etile[d * ET_PITCH + mm];
                myrow[mt * ADJ_TILE + mm] = s;       // raw s (relu folded into max)
            }
            __syncthreads();
        }

        // ---- row max (relu implied: lmax starts at 0) ----
        float lmax = 0.0f;
#pragma unroll 4
        for (int m = lane; m < NN; m += 32) lmax = fmaxf(lmax, myrow[m]);
#pragma unroll
        for (int off = 16; off > 0; off >>= 1)
            lmax = fmaxf(lmax, __shfl_xor_sync(0xffffffffu, lmax, off));

        // ---- exp + sum + store unnormalized fp16 ----
        float lsum = 0.f;
#pragma unroll 4
        for (int m = lane; m < NN; m += 32) {
            float v = expf(fmaxf(myrow[m], 0.0f) - lmax);
            lsum += v;
            g_Ah[(size_t)n * NN + m] = __float2half(v);
        }
#pragma unroll
        for (int off = 16; off > 0; off >>= 1)
            lsum += __shfl_xor_sync(0xffffffffu, lsum, off);
        if (lane == 0) g_inv[n] = 1.0f / lsum;
    } else {
        // ----- feat transpose + fp16 convert (writes XTh and Fnh [N,B,C]) -----
        const int bid2 = blockIdx.x - 256;
        const int m0 = (bid2 & 31) * 64;
        const int b  = bid2 >> 5;
        float (*tile)[65] = (float(*)[65])praw;

        const int mr = t >> 4, c4 = (t & 15) * 4;
#pragma unroll
        for (int p = 0; p < 4; p++) {
            const int m = m0 + mr + p * 16;
            float4 v = *(const float4*)(feat + ((size_t)b * NN + m) * CC + c4);
            tile[mr + p * 16][c4 + 0] = v.x;
            tile[mr + p * 16][c4 + 1] = v.y;
            tile[mr + p * 16][c4 + 2] = v.z;
            tile[mr + p * 16][c4 + 3] = v.w;
            __half2 h0 = __floats2half2_rn(v.x, v.y);
            __half2 h1 = __floats2half2_rn(v.z, v.w);
            *(uint2*)(g_Fnh + ((size_t)m * BB + b) * CC + c4) =
                make_uint2(*(uint32_t*)&h0, *(uint32_t*)&h1);
        }
        __syncthreads();

        const int cl = t >> 4, m4 = (t & 15) * 4;
#pragma unroll
        for (int p = 0; p < 4; p++) {
            int c = cl + p * 16;
            __half2 p0 = __floats2half2_rn(tile[m4 + 0][c], tile[m4 + 1][c]);
            __half2 p1 = __floats2half2_rn(tile[m4 + 2][c], tile[m4 + 3][c]);
            *(uint2*)(g_XTh + (size_t)(b * 64 + c) * NN + m0 + m4) =
                make_uint2(*(uint32_t*)&p0, *(uint32_t*)&p1);
        }
    }
}

// ---------------------------------------------------------------------------
// compute_weights as a 128-thread device block (folded into gemm<0> launch)
// ---------------------------------------------------------------------------
__device__ void cw_block(char* smem, const float* __restrict__ E,
                         const float* __restrict__ Wp, int cwid)
{
    const int col0 = (cwid % 96) * 128;
    const int n0   = (cwid / 96) * 64;
    const int t    = threadIdx.x;   // 0..127

    float* ws = (float*)smem;        // [16][128]
    float* es = ws + DD * 128;       // [64][16]

#pragma unroll
    for (int i = 0; i < 4; i++) {
        int idx = t + i * 128;
        int r = idx >> 5;
        int c = (idx & 31) * 4;
        *(float4*)&ws[r * 128 + c] = *(const float4*)(Wp + (size_t)r * WCOLS + col0 + c);
    }
#pragma unroll
    for (int i = 0; i < 2; i++) {
        int idx = t + i * 128;
        int r = idx >> 2;
        int c = (idx & 3) * 4;
        *(float4*)&es[r * DD + c] = *(const float4*)(E + (n0 + r) * DD + c);
    }
    __syncthreads();

    const int tx = t & 31;
    const int ty = t >> 5;
#pragma unroll
    for (int nn = ty; nn < 64; nn += 4) {
        float4 acc = make_float4(0.f, 0.f, 0.f, 0.f);
#pragma unroll
        for (int d = 0; d < DD; d++) {
            float ev = es[nn * DD + d];
            float4 w = *(const float4*)&ws[d * 128 + tx * 4];
            acc.x += ev * w.x; acc.y += ev * w.y;
            acc.z += ev * w.z; acc.w += ev * w.w;
        }
        __half2 h0 = __floats2half2_rn(acc.x, acc.y);
        __half2 h1 = __floats2half2_rn(acc.z, acc.w);
        *(uint2*)(g_Wh + (size_t)(n0 + nn) * WCOLS + col0 + tx * 4) =
            make_uint2(*(uint32_t*)&h0, *(uint32_t*)&h1);
    }
}

// ---------------------------------------------------------------------------
// final_gconv as a 128-thread device block (folded into gemm<1> launch).
// Waits on gemm1 m-stripe for its node (cw completed in launch 2).
// ---------------------------------------------------------------------------
#define FG_A_OFF   0       // 3 * 8192 = 24576
#define FG_B_OFF   24576   // 192 * 128 = 24576
#define FG_BIAS    49152   // 64 floats
#define FG_OPITCH  68

__device__ void final_block(char* sal, uint32_t sb, int n,
                            const float* __restrict__ E,
                            const float* __restrict__ biasP,
                            float* __restrict__ out)
{
    const int t    = threadIdx.x;   // 0..127
    const int lane = t & 31;
    const int wid  = t >> 5;
    const int wm   = wid >> 1;      // 0..1 : b rows wm*32
    const int wn   = wid & 1;       // 0..1 : o cols wn*32

    if (t == 0) {
        while (atomicAdd(&g_stripe_cnt[n >> 7], 0) < 32) __nanosleep(64);
        __threadfence();
    }
    __syncthreads();

    const char* asrc[KK] = {
        (const char*)(g_Fnh  + (size_t)n * (BB * CC)),
        (const char*)(g_Y1nh + (size_t)n * (BB * CC)),
        (const char*)(g_Y2nh + (size_t)n * (BB * CC)) };
    const char* wsrc = (const char*)(g_Wh + (size_t)n * WCOLS);
#pragma unroll
    for (int p = 0; p < 3; p++) {
#pragma unroll
        for (int i = 0; i < 4; i++) {
            int idx = t + i * 128;
            uint32_t so = SWZ((uint32_t)(idx * 16));
            CP_ASYNC16(sb + FG_A_OFF + p * 8192 + so, asrc[p] + idx * 16);
        }
#pragma unroll
        for (int i = 0; i < 4; i++) {
            int idx = p * 512 + t + i * 128;
            uint32_t so = SWZ((uint32_t)(idx * 16));
            CP_ASYNC16(sb + FG_B_OFF + so, wsrc + (size_t)idx * 16);
        }
        CP_COMMIT();
    }

    float* bias_s = (float*)(sal + FG_BIAS);
    if (t < OO) {
        float s = 0.f;
#pragma unroll
        for (int d = 0; d < DD; d++) s += E[n * DD + d] * biasP[d * OO + t];
        bias_s[t] = s;
    }

    float acc[2][4][4];
#pragma unroll
    for (int mf = 0; mf < 2; mf++)
#pragma unroll
        for (int nf = 0; nf < 4; nf++)
#pragma unroll
            for (int q = 0; q < 4; q++) acc[mf][nf][q] = 0.f;

    const int a_row  = lane & 15;
    const int a_kofs = (lane >> 4) << 4;
    const int bt_row = lane & 15;
    const int bt_col = (lane >> 4) << 3;

#pragma unroll
    for (int p = 0; p < 3; p++) {
        if (p == 0) { CP_WAIT2(); } else if (p == 1) { CP_WAIT1(); } else { CP_WAIT0(); }
        __syncthreads();
#pragma unroll
        for (int kko = 0; kko < 4; kko++) {
            const int kk = p * 4 + kko;
            uint32_t a[2][4], b[2][4];
#pragma unroll
            for (int mf = 0; mf < 2; mf++)
                ldsm4(a[mf], sb + FG_A_OFF + p * 8192 +
                      SWZ((uint32_t)((wm * 32 + mf * 16 + a_row) * 128 + kko * 32 + a_kofs)));
#pragma unroll
            for (int j = 0; j < 2; j++)
                ldsm4t(b[j], sb + FG_B_OFF +
                       SWZ((uint32_t)((kk * 16 + bt_row) * 128 + (wn * 32 + j * 16 + bt_col) * 2)));
#pragma unroll
            for (int mf = 0; mf < 2; mf++)
#pragma unroll
                for (int j = 0; j < 2; j++) {
                    mma16816(acc[mf][j * 2 + 0], a[mf], &b[j][0]);
                    mma16816(acc[mf][j * 2 + 1], a[mf], &b[j][2]);
                }
        }
    }
    __syncthreads();

    float* osm = (float*)sal;
#pragma unroll
    for (int mf = 0; mf < 2; mf++)
#pragma unroll
        for (int nf = 0; nf < 4; nf++) {
            int r = wm * 32 + mf * 16 + (lane >> 2);
            int c = wn * 32 + nf * 8 + (lane & 3) * 2;
            osm[r * FG_OPITCH + c]           = acc[mf][nf][0];
            osm[r * FG_OPITCH + c + 1]       = acc[mf][nf][1];
            osm[(r + 8) * FG_OPITCH + c]     = acc[mf][nf][2];
            osm[(r + 8) * FG_OPITCH + c + 1] = acc[mf][nf][3];
        }
    __syncthreads();

    const int b  = t >> 1;
    const int q0 = (t & 1) * 32;
    float* dst = out + ((size_t)b * NN + n) * OO + q0;
#pragma unroll
    for (int i = 0; i < 8; i++) {
        float4 v = *(float4*)&osm[b * FG_OPITCH + q0 + i * 4];
        v.x += bias_s[q0 + i * 4 + 0];
        v.y += bias_s[q0 + i * 4 + 1];
        v.z += bias_s[q0 + i * 4 + 2];
        v.w += bias_s[q0 + i * 4 + 3];
        *(float4*)(dst + i * 4) = v;
    }
}

// ---------------------------------------------------------------------------
// Kernel 2: mma.sync fp16 GEMM.  D[n, bc] = inv[n] * sum_m Ah[n,m] * B[bc, m]
//   PASS 0: B = g_XTh ; writes g_Y1nh + g_Y1Th.  bid >= 512 -> cw_block.
//   PASS 1: B = g_Y1Th; writes g_Y2nh; stripe counters; bid >= 512 -> final.
// ---------------------------------------------------------------------------
#define MT 128
#define NT 128
#define KCH 64
#define NCH (NN / KCH)     // 32
#define ASTG (MT * 128)    // 16 KB
#define BSTG (NT * 128)    // 16 KB
#define STG_BYTES (ASTG + BSTG)
#define STAGES 3
#define EPI_PITCH 132
#define GEMM_SMEM (STAGES * STG_BYTES + 1024)
#define GEMM_CTAS ((NN / MT) * (BC / NT))     // 512
#define CW_CTAS   ((WCOLS / 128) * (NN / 64)) // 3072

template <int PASS>
__global__ void __launch_bounds__(128, 2) gemm_mma(
    const float* __restrict__ feat,
    const float* __restrict__ E,
    const float* __restrict__ Wp,
    const float* __restrict__ biasP,
    float* __restrict__ out)
{
    extern __shared__ char smem_raw[];
    char* sal = (char*)(((uintptr_t)smem_raw + 1023) & ~(uintptr_t)1023);
    const uint32_t sb = smem_u32(sal);

    if (PASS == 0 && blockIdx.x >= GEMM_CTAS) {
        cw_block(smem_raw, E, Wp, blockIdx.x - GEMM_CTAS);
        return;
    }
    if (PASS == 1 && blockIdx.x >= GEMM_CTAS) {
        final_block(sal, sb, blockIdx.x - GEMM_CTAS, E, biasP, out);
        return;
    }

    const int t    = threadIdx.x;
    const int lane = t & 31;
    const int wid  = t >> 5;
    const int wm   = wid >> 1;
    const int wn   = wid & 1;
    const int m0   = PASS ? (blockIdx.x >> 5) * MT : (blockIdx.x & 15) * MT;
    const int n0   = PASS ? (blockIdx.x & 31) * NT : (blockIdx.x >> 4) * NT;

    const __half* __restrict__ Bsrc = PASS ? g_Y1Th : g_XTh;

    float acc[4][8][4];
#pragma unroll
    for (int i = 0; i < 4; i++)
#pragma unroll
        for (int j = 0; j < 8; j++)
#pragma unroll
            for (int q = 0; q < 4; q++) acc[i][j][q] = 0.f;

    auto load_chunk = [&](int ch, int s) {
        const uint32_t stA = sb + s * STG_BYTES;
        const uint32_t stB = stA + ASTG;
        const __half* agp = g_Ah + (size_t)m0 * NN + ch * KCH;
        const __half* bgp = Bsrc + (size_t)n0 * NN + ch * KCH;
#pragma unroll
        for (int i = 0; i < 8; i++) {
            int idx = t + i * 128;
            int r = idx >> 3, c = idx & 7;
            uint32_t so = SWZ((uint32_t)(r * 128 + c * 16));
            CP_ASYNC16(stA + so, agp + (size_t)r * NN + c * 8);
            CP_ASYNC16(stB + so, bgp + (size_t)r * NN + c * 8);
        }
        CP_COMMIT();
    };

    load_chunk(0, 0);
    load_chunk(1, 1);

    const int a_row  = (lane & 15);
    const int a_kofs = (lane >> 4) << 4;
    const int b_row  = ((lane >> 4) << 3) + (lane & 7);
    const int b_kofs = ((lane >> 3) & 1) << 4;

    for (int ch = 0; ch < NCH; ch++) {
        const int s = ch % STAGES;
        if (ch >= NCH - 2) { CP_WAIT0(); } else { CP_WAIT1(); }
        __syncthreads();
        if (ch + 2 < NCH) load_chunk(ch + 2, (ch + 2) % STAGES);

        const uint32_t stA = sb + s * STG_BYTES;
        const uint32_t stB = stA + ASTG;
#pragma unroll
        for (int kk = 0; kk < 4; kk++) {
            uint32_t a[4][4], b[4][4];
#pragma unroll
            for (int mf = 0; mf < 4; mf++) {
                int r = wm * 64 + mf * 16 + a_row;
                ldsm4(a[mf], stA + SWZ((uint32_t)(r * 128 + kk * 32 + a_kofs)));
            }
#pragma unroll
            for (int nf2 = 0; nf2 < 4; nf2++) {
                int r = wn * 64 + nf2 * 16 + b_row;
                ldsm4(b[nf2], stB + SWZ((uint32_t)(r * 128 + kk * 32 + b_kofs)));
            }
#pragma unroll
            for (int mf = 0; mf < 4; mf++)
#pragma unroll
                for (int nf = 0; nf < 8; nf++)
                    mma16816(acc[mf][nf], a[mf], &b[nf >> 1][(nf & 1) * 2]);
        }
    }
    __syncthreads();

    // ---- epilogue: stage accumulators through smem (fp32) ----
    float* esm = (float*)sal;
#pragma unroll
    for (int mf = 0; mf < 4; mf++) {
#pragma unroll
        for (int nf = 0; nf < 8; nf++) {
            int r = wm * 64 + mf * 16 + (lane >> 2);
            int c = wn * 64 + nf * 8 + (lane & 3) * 2;
            esm[r * EPI_PITCH + c]           = acc[mf][nf][0];
            esm[r * EPI_PITCH + c + 1]       = acc[mf][nf][1];
            esm[(r + 8) * EPI_PITCH + c]     = acc[mf][nf][2];
            esm[(r + 8) * EPI_PITCH + c + 1] = acc[mf][nf][3];
        }
    }
    __syncthreads();

    const int r = t;               // 0..127
    const int n = m0 + r;
    const float inv = g_inv[n];    // softmax row normalization (folded)
    if (PASS == 0) {
#pragma unroll
        for (int h = 0; h < 2; h++) {   // g_Y1nh fp16 [N,B,C]
            const int b = (n0 >> 6) + h;
            uint4* dst = (uint4*)(g_Y1nh + ((size_t)n * BB + b) * CC);
#pragma unroll
            for (int i = 0; i < 8; i++) {
                float4 v0 = *(float4*)&esm[r * EPI_PITCH + h * 64 + i * 8];
                float4 v1 = *(float4*)&esm[r * EPI_PITCH + h * 64 + i * 8 + 4];
                __half2 a0 = __floats2half2_rn(v0.x * inv, v0.y * inv);
                __half2 a1 = __floats2half2_rn(v0.z * inv, v0.w * inv);
                __half2 a2 = __floats2half2_rn(v1.x * inv, v1.y * inv);
                __half2 a3 = __floats2half2_rn(v1.z * inv, v1.w * inv);
                dst[i] = make_uint4(*(uint32_t*)&a0, *(uint32_t*)&a1,
                                    *(uint32_t*)&a2, *(uint32_t*)&a3);
            }
        }
        {   // g_Y1Th fp16 [bc][m]
            const int j = r;
            uint4* d4 = (uint4*)(g_Y1Th + (size_t)(n0 + j) * NN + m0);
#pragma unroll
            for (int q = 0; q < 16; q++) {
                uint32_t p[4];
#pragma unroll
                for (int u = 0; u < 4; u++) {
                    int rr = q * 8 + u * 2;
                    __half2 hv = __floats2half2_rn(
                        esm[rr * EPI_PITCH + j]       * g_inv[m0 + rr],
                        esm[(rr + 1) * EPI_PITCH + j] * g_inv[m0 + rr + 1]);
                    p[u] = *(uint32_t*)&hv;
                }
                d4[q] = make_uint4(p[0], p[1], p[2], p[3]);
            }
        }
    } else {
#pragma unroll
        for (int h = 0; h < 2; h++) {
            const int b = (n0 >> 6) + h;
            const float4* fsrc = (const float4*)(feat + ((size_t)b * NN + n) * CC);
            uint4* dst = (uint4*)(g_Y2nh + ((size_t)n * BB + b) * CC);
            const float s2 = 2.f * inv;
#pragma unroll
            for (int i = 0; i < 8; i++) {
                float4 v0 = *(float4*)&esm[r * EPI_PITCH + h * 64 + i * 8];
                float4 v1 = *(float4*)&esm[r * EPI_PITCH + h * 64 + i * 8 + 4];
                float4 f0 = fsrc[i * 2], f1 = fsrc[i * 2 + 1];
                __half2 a0 = __floats2half2_rn(s2 * v0.x - f0.x, s2 * v0.y - f0.y);
                __half2 a1 = __floats2half2_rn(s2 * v0.z - f0.z, s2 * v0.w - f0.w);
                __half2 a2 = __floats2half2_rn(s2 * v1.x - f1.x, s2 * v1.y - f1.y);
                __half2 a3 = __floats2half2_rn(s2 * v1.z - f1.z, s2 * v1.w - f1.w);
                dst[i] = make_uint4(*(uint32_t*)&a0, *(uint32_t*)&a1,
                                    *(uint32_t*)&a2, *(uint32_t*)&a3);
            }
        }
        __syncthreads();
        if (t == 0) {
            __threadfence();
            atomicAdd(&g_stripe_cnt[(unsigned)m0 >> 7], 1);
        }
    }
}

// ---------------------------------------------------------------------------
extern "C" void kernel_launch(void* const* d_in, const int* in_sizes, int n_in,
                              void* d_out, int out_size)
{
    const float* E     = (const float*)d_in[0];  // [2048,16]
    const float* feat  = (const float*)d_in[1];  // [64,2048,64]
    const float* Wp    = (const float*)d_in[2];  // [16,3,64,64]
    const float* biasP = (const float*)d_in[3];  // [16,64]
    float* out = (float*)d_out;                  // [64,2048,64]

    cudaFuncSetAttribute(prep_kernel, cudaFuncAttributeMaxDynamicSharedMemorySize, PREP_SMEM);
    cudaFuncSetAttribute(gemm_mma<0>, cudaFuncAttributeMaxDynamicSharedMemorySize, GEMM_SMEM);
    cudaFuncSetAttribute(gemm_mma<1>, cudaFuncAttributeMaxDynamicSharedMemorySize, GEMM_SMEM);

    prep_kernel<<<256 + 2048, 256, PREP_SMEM>>>(E, feat);
    gemm_mma<0><<<GEMM_CTAS + CW_CTAS, 128, GEMM_SMEM>>>(feat, E, Wp, biasP, out);
    gemm_mma<1><<<GEMM_CTAS + NN, 128, GEMM_SMEM>>>(feat, E, Wp, biasP, out);
}

// round 15
// speedup vs baseline: 1.0506x; 1.0013x over previous
#include <cuda_runtime.h>
#include <cuda_fp16.h>
#include <cstdint>

// Problem constants
#define NN 2048      // nodes
#define DD 16        // embedding dim
#define BB 64        // batch
#define CC 64        // in channels
#define OO 64        // out channels
#define KK 3         // cheb order
#define KC (KK*CC)   // 192
#define WCOLS (KC*OO) // 12288
#define BC (BB*CC)   // 4096 columns of the big GEMM

// ---------------- scratch (static device allocations allowed) ----------------
__device__ __half g_Ah  [(size_t)NN * NN];      // 8 MB : exp(relu(sim)-max) fp16 (UNNORMALIZED)
__device__ float  g_inv [NN];                   // per-row 1/sum for softmax
__device__ __half g_XTh [(size_t)BC * NN];      // 16 MB: XT[bc][m] = feat[b][m][c]
__device__ __half g_Y1Th[(size_t)BC * NN];      // 16 MB: Y1 transposed (pass-1 B)
__device__ __half g_Fnh [(size_t)NN * BB * CC]; // 16 MB: feat fp16 [N,B,C]
__device__ __half g_Y1nh[(size_t)NN * BB * CC]; // 16 MB: Y1  fp16 [N,B,C]
__device__ __half g_Y2nh[(size_t)NN * BB * CC]; // 16 MB: Y2  fp16 [N,B,C]
__device__ __half g_Wh  [(size_t)NN * WCOLS];   // 50 MB: per-node weights fp16
__device__ int    g_stripe_cnt[16];             // gemm<1> m-stripe completion

// ---------------- PTX helpers (baseline ISA only) ----------------
__device__ __forceinline__ uint32_t smem_u32(const void* p) {
    uint32_t a;
    asm("{ .reg .u64 t; cvta.to.shared.u64 t, %1; cvt.u32.u64 %0, t; }" : "=r"(a) : "l"(p));
    return a;
}
#define CP_ASYNC16(dst, src) \
    asm volatile("cp.async.cg.shared.global [%0], [%1], 16;" :: "r"(dst), "l"(src))
#define CP_COMMIT() asm volatile("cp.async.commit_group;" ::: "memory")
#define CP_WAIT2()  asm volatile("cp.async.wait_group 2;" ::: "memory")
#define CP_WAIT1()  asm volatile("cp.async.wait_group 1;" ::: "memory")
#define CP_WAIT0()  asm volatile("cp.async.wait_group 0;" ::: "memory")

__device__ __forceinline__ void ldsm4(uint32_t* r, uint32_t addr) {
    asm volatile("ldmatrix.sync.aligned.m8n8.x4.shared.b16 {%0,%1,%2,%3}, [%4];"
        : "=r"(r[0]), "=r"(r[1]), "=r"(r[2]), "=r"(r[3]) : "r"(addr));
}
__device__ __forceinline__ void ldsm4t(uint32_t* r, uint32_t addr) {
    asm volatile("ldmatrix.sync.aligned.m8n8.x4.trans.shared.b16 {%0,%1,%2,%3}, [%4];"
        : "=r"(r[0]), "=r"(r[1]), "=r"(r[2]), "=r"(r[3]) : "r"(addr));
}
__device__ __forceinline__ void mma16816(float* d, const uint32_t* a, const uint32_t* b) {
    asm volatile("mma.sync.aligned.m16n8k16.row.col.f32.f16.f16.f32 "
        "{%0,%1,%2,%3}, {%4,%5,%6,%7}, {%8,%9}, {%0,%1,%2,%3};"
        : "+f"(d[0]), "+f"(d[1]), "+f"(d[2]), "+f"(d[3])
        : "r"(a[0]), "r"(a[1]), "r"(a[2]), "r"(a[3]), "r"(b[0]), "r"(b[1]));
}
#define SWZ(o) ((o) ^ (((o) >> 3) & 0x70))

// ---------------------------------------------------------------------------
// Kernel 1 (fused prep): blocks [0,256)  -> adjacency exp (8 rows per block)
//                        blocks [256, 2304) -> feat transpose / fp16 convert
// Adjacency: SINGLE pass of dot products into a smem row buffer; E-tile held
// TRANSPOSED [d][m] pitch 258 (conflict-free). Stores UNNORMALIZED
// exp(s - rowmax) fp16 + g_inv[n]; GEMM epilogue applies inv.
// ---------------------------------------------------------------------------
#define ADJ_TILE 256
#define ET_PITCH 258
#define ET_BYTES (DD * ET_PITCH * 4)          // 16512
#define PREP_SMEM (ET_BYTES + 8 * NN * 4)     // 16512 + 65536 = 82048

__global__ void __launch_bounds__(256) prep_kernel(
    const float* __restrict__ E, const float* __restrict__ feat)
{
    extern __shared__ char praw[];
    const int t = threadIdx.x;

    if (blockIdx.x < 256) {
        if (blockIdx.x == 0 && t < 16) g_stripe_cnt[t] = 0;

        float* etile = (float*)praw;                 // [16][258] transposed
        float* rows  = (float*)(praw + ET_BYTES);    // [8][2048]
        const int lane = t & 31;
        const int w    = t >> 5;
        const int n    = blockIdx.x * 8 + w;

        float e[DD];
#pragma unroll
        for (int d = 0; d < DD; d++) e[d] = E[n * DD + d];

        float* myrow = rows + w * NN;

        // ---- single pass: dots into row buffer ----
        for (int mt = 0; mt < NN / ADJ_TILE; mt++) {
#pragma unroll
            for (int i = 0; i < 4; i++) {            // transposed tile load
                int idx = t + i * 256;               // 0..1023 float4s
                int r   = idx >> 2;
                int c4  = (idx & 3) * 4;
                float4 v = *(const float4*)(E + (size_t)(mt * ADJ_TILE + r) * DD + c4);
                etile[(c4 + 0) * ET_PITCH + r] = v.x;
                etile[(c4 + 1) * ET_PITCH + r] = v.y;
                etile[(c4 + 2) * ET_PITCH + r] = v.z;
                etile[(c4 + 3) * ET_PITCH + r] = v.w;
            }
            __syncthreads();
#pragma unroll 2
            for (int j = 0; j < ADJ_TILE / 32; j++) {
                int mm = j * 32 + lane;
                float s = 0.f;
#pragma unroll
                for (int d = 0; d < DD; d++) s += e[d] * etile[d * ET_PITCH + mm];
                myrow[mt * ADJ_TILE + mm] = s;       // raw s (relu folded into max)
            }
            __syncthreads();
        }

        // ---- row max (relu implied: lmax starts at 0) ----
        float lmax = 0.0f;
#pragma unroll 4
        for (int m = lane; m < NN; m += 32) lmax = fmaxf(lmax, myrow[m]);
#pragma unroll
        for (int off = 16; off > 0; off >>= 1)
            lmax = fmaxf(lmax, __shfl_xor_sync(0xffffffffu, lmax, off));

        // ---- exp + sum + store unnormalized fp16 ----
        float lsum = 0.f;
#pragma unroll 4
        for (int m = lane; m < NN; m += 32) {
            float v = expf(fmaxf(myrow[m], 0.0f) - lmax);
            lsum += v;
            g_Ah[(size_t)n * NN + m] = __float2half(v);
        }
#pragma unroll
        for (int off = 16; off > 0; off >>= 1)
            lsum += __shfl_xor_sync(0xffffffffu, lsum, off);
        if (lane == 0) g_inv[n] = 1.0f / lsum;
    } else {
        // ----- feat transpose + fp16 convert (writes XTh and Fnh [N,B,C]) -----
        const int bid2 = blockIdx.x - 256;
        const int m0 = (bid2 & 31) * 64;
        const int b  = bid2 >> 5;
        float (*tile)[65] = (float(*)[65])praw;

        const int mr = t >> 4, c4 = (t & 15) * 4;
#pragma unroll
        for (int p = 0; p < 4; p++) {
            const int m = m0 + mr + p * 16;
            float4 v = *(const float4*)(feat + ((size_t)b * NN + m) * CC + c4);
            tile[mr + p * 16][c4 + 0] = v.x;
            tile[mr + p * 16][c4 + 1] = v.y;
            tile[mr + p * 16][c4 + 2] = v.z;
            tile[mr + p * 16][c4 + 3] = v.w;
            __half2 h0 = __floats2half2_rn(v.x, v.y);
            __half2 h1 = __floats2half2_rn(v.z, v.w);
            *(uint2*)(g_Fnh + ((size_t)m * BB + b) * CC + c4) =
                make_uint2(*(uint32_t*)&h0, *(uint32_t*)&h1);
        }
        __syncthreads();

        const int cl = t >> 4, m4 = (t & 15) * 4;
#pragma unroll
        for (int p = 0; p < 4; p++) {
            int c = cl + p * 16;
            __half2 p0 = __floats2half2_rn(tile[m4 + 0][c], tile[m4 + 1][c]);
            __half2 p1 = __floats2half2_rn(tile[m4 + 2][c], tile[m4 + 3][c]);
            *(uint2*)(g_XTh + (size_t)(b * 64 + c) * NN + m0 + m4) =
                make_uint2(*(uint32_t*)&p0, *(uint32_t*)&p1);
        }
    }
}

// ---------------------------------------------------------------------------
// compute_weights as a 128-thread device block (folded into gemm<0> launch)
// ---------------------------------------------------------------------------
__device__ void cw_block(char* smem, const float* __restrict__ E,
                         const float* __restrict__ Wp, int cwid)
{
    const int col0 = (cwid % 96) * 128;
    const int n0   = (cwid / 96) * 64;
    const int t    = threadIdx.x;   // 0..127

    float* ws = (float*)smem;        // [16][128]
    float* es = ws + DD * 128;       // [64][16]

#pragma unroll
    for (int i = 0; i < 4; i++) {
        int idx = t + i * 128;
        int r = idx >> 5;
        int c = (idx & 31) * 4;
        *(float4*)&ws[r * 128 + c] = *(const float4*)(Wp + (size_t)r * WCOLS + col0 + c);
    }
#pragma unroll
    for (int i = 0; i < 2; i++) {
        int idx = t + i * 128;
        int r = idx >> 2;
        int c = (idx & 3) * 4;
        *(float4*)&es[r * DD + c] = *(const float4*)(E + (n0 + r) * DD + c);
    }
    __syncthreads();

    const int tx = t & 31;
    const int ty = t >> 5;
#pragma unroll
    for (int nn = ty; nn < 64; nn += 4) {
        float4 acc = make_float4(0.f, 0.f, 0.f, 0.f);
#pragma unroll
        for (int d = 0; d < DD; d++) {
            float ev = es[nn * DD + d];
            float4 w = *(const float4*)&ws[d * 128 + tx * 4];
            acc.x += ev * w.x; acc.y += ev * w.y;
            acc.z += ev * w.z; acc.w += ev * w.w;
        }
        __half2 h0 = __floats2half2_rn(acc.x, acc.y);
        __half2 h1 = __floats2half2_rn(acc.z, acc.w);
        *(uint2*)(g_Wh + (size_t)(n0 + nn) * WCOLS + col0 + tx * 4) =
            make_uint2(*(uint32_t*)&h0, *(uint32_t*)&h1);
    }
}

// ---------------------------------------------------------------------------
// final_gconv as a 128-thread device block (folded into gemm<1> launch).
// Waits on gemm1 m-stripe for its node (cw completed in launch 2).
// ---------------------------------------------------------------------------
#define FG_A_OFF   0       // 3 * 8192 = 24576
#define FG_B_OFF   24576   // 192 * 128 = 24576
#define FG_BIAS    49152   // 64 floats
#define FG_OPITCH  68

__device__ void final_block(char* sal, uint32_t sb, int n,
                            const float* __restrict__ E,
                            const float* __restrict__ biasP,
                            float* __restrict__ out)
{
    const int t    = threadIdx.x;   // 0..127
    const int lane = t & 31;
    const int wid  = t >> 5;
    const int wm   = wid >> 1;      // 0..1 : b rows wm*32
    const int wn   = wid & 1;       // 0..1 : o cols wn*32

    if (t == 0) {
        while (atomicAdd(&g_stripe_cnt[n >> 7], 0) < 32) __nanosleep(64);
        __threadfence();
    }
    __syncthreads();

    const char* asrc[KK] = {
        (const char*)(g_Fnh  + (size_t)n * (BB * CC)),
        (const char*)(g_Y1nh + (size_t)n * (BB * CC)),
        (const char*)(g_Y2nh + (size_t)n * (BB * CC)) };
    const char* wsrc = (const char*)(g_Wh + (size_t)n * WCOLS);
#pragma unroll
    for (int p = 0; p < 3; p++) {
#pragma unroll
        for (int i = 0; i < 4; i++) {
            int idx = t + i * 128;
            uint32_t so = SWZ((uint32_t)(idx * 16));
            CP_ASYNC16(sb + FG_A_OFF + p * 8192 + so, asrc[p] + idx * 16);
        }
#pragma unroll
        for (int i = 0; i < 4; i++) {
            int idx = p * 512 + t + i * 128;
            uint32_t so = SWZ((uint32_t)(idx * 16));
            CP_ASYNC16(sb + FG_B_OFF + so, wsrc + (size_t)idx * 16);
        }
        CP_COMMIT();
    }

    float* bias_s = (float*)(sal + FG_BIAS);
    if (t < OO) {
        float s = 0.f;
#pragma unroll
        for (int d = 0; d < DD; d++) s += E[n * DD + d] * biasP[d * OO + t];
        bias_s[t] = s;
    }

    float acc[2][4][4];
#pragma unroll
    for (int mf = 0; mf < 2; mf++)
#pragma unroll
        for (int nf = 0; nf < 4; nf++)
#pragma unroll
            for (int q = 0; q < 4; q++) acc[mf][nf][q] = 0.f;

    const int a_row  = lane & 15;
    const int a_kofs = (lane >> 4) << 4;
    const int bt_row = lane & 15;
    const int bt_col = (lane >> 4) << 3;

#pragma unroll
    for (int p = 0; p < 3; p++) {
        if (p == 0) { CP_WAIT2(); } else if (p == 1) { CP_WAIT1(); } else { CP_WAIT0(); }
        __syncthreads();
#pragma unroll
        for (int kko = 0; kko < 4; kko++) {
            const int kk = p * 4 + kko;
            uint32_t a[2][4], b[2][4];
#pragma unroll
            for (int mf = 0; mf < 2; mf++)
                ldsm4(a[mf], sb + FG_A_OFF + p * 8192 +
                      SWZ((uint32_t)((wm * 32 + mf * 16 + a_row) * 128 + kko * 32 + a_kofs)));
#pragma unroll
            for (int j = 0; j < 2; j++)
                ldsm4t(b[j], sb + FG_B_OFF +
                       SWZ((uint32_t)((kk * 16 + bt_row) * 128 + (wn * 32 + j * 16 + bt_col) * 2)));
#pragma unroll
            for (int mf = 0; mf < 2; mf++)
#pragma unroll
                for (int j = 0; j < 2; j++) {
                    mma16816(acc[mf][j * 2 + 0], a[mf], &b[j][0]);
                    mma16816(acc[mf][j * 2 + 1], a[mf], &b[j][2]);
                }
        }
    }
    __syncthreads();

    float* osm = (float*)sal;
#pragma unroll
    for (int mf = 0; mf < 2; mf++)
#pragma unroll
        for (int nf = 0; nf < 4; nf++) {
            int r = wm * 32 + mf * 16 + (lane >> 2);
            int c = wn * 32 + nf * 8 + (lane & 3) * 2;
            osm[r * FG_OPITCH + c]           = acc[mf][nf][0];
            osm[r * FG_OPITCH + c + 1]       = acc[mf][nf][1];
            osm[(r + 8) * FG_OPITCH + c]     = acc[mf][nf][2];
            osm[(r + 8) * FG_OPITCH + c + 1] = acc[mf][nf][3];
        }
    __syncthreads();

    const int b  = t >> 1;
    const int q0 = (t & 1) * 32;
    float* dst = out + ((size_t)b * NN + n) * OO + q0;
#pragma unroll
    for (int i = 0; i < 8; i++) {
        float4 v = *(float4*)&osm[b * FG_OPITCH + q0 + i * 4];
        v.x += bias_s[q0 + i * 4 + 0];
        v.y += bias_s[q0 + i * 4 + 1];
        v.z += bias_s[q0 + i * 4 + 2];
        v.w += bias_s[q0 + i * 4 + 3];
        *(float4*)(dst + i * 4) = v;
    }
}

// ---------------------------------------------------------------------------
// Kernel 2: mma.sync fp16 GEMM.  D[n, bc] = inv[n] * sum_m Ah[n,m] * B[bc, m]
//   PASS 0: B = g_XTh ; writes g_Y1nh + g_Y1Th.  bid >= 512 -> cw_block.
//   PASS 1: B = g_Y1Th; writes g_Y2nh; stripe counters; bid >= 512 -> final.
// ---------------------------------------------------------------------------
#define MT 128
#define NT 128
#define KCH 64
#define NCH (NN / KCH)     // 32
#define ASTG (MT * 128)    // 16 KB
#define BSTG (NT * 128)    // 16 KB
#define STG_BYTES (ASTG + BSTG)
#define STAGES 3
#define EPI_PITCH 132
#define GEMM_SMEM (STAGES * STG_BYTES + 1024)
#define GEMM_CTAS ((NN / MT) * (BC / NT))     // 512
#define CW_CTAS   ((WCOLS / 128) * (NN / 64)) // 3072

template <int PASS>
__global__ void __launch_bounds__(128, 2) gemm_mma(
    const float* __restrict__ feat,
    const float* __restrict__ E,
    const float* __restrict__ Wp,
    const float* __restrict__ biasP,
    float* __restrict__ out)
{
    extern __shared__ char smem_raw[];
    char* sal = (char*)(((uintptr_t)smem_raw + 1023) & ~(uintptr_t)1023);
    const uint32_t sb = smem_u32(sal);

    if (PASS == 0 && blockIdx.x >= GEMM_CTAS) {
        cw_block(smem_raw, E, Wp, blockIdx.x - GEMM_CTAS);
        return;
    }
    if (PASS == 1 && blockIdx.x >= GEMM_CTAS) {
        final_block(sal, sb, blockIdx.x - GEMM_CTAS, E, biasP, out);
        return;
    }

    const int t    = threadIdx.x;
    const int lane = t & 31;
    const int wid  = t >> 5;
    const int wm   = wid >> 1;
    const int wn   = wid & 1;
    const int m0   = PASS ? (blockIdx.x >> 5) * MT : (blockIdx.x & 15) * MT;
    const int n0   = PASS ? (blockIdx.x & 31) * NT : (blockIdx.x >> 4) * NT;

    const __half* __restrict__ Bsrc = PASS ? g_Y1Th : g_XTh;

    float acc[4][8][4];
#pragma unroll
    for (int i = 0; i < 4; i++)
#pragma unroll
        for (int j = 0; j < 8; j++)
#pragma unroll
            for (int q = 0; q < 4; q++) acc[i][j][q] = 0.f;

    auto load_chunk = [&](int ch, int s) {
        const uint32_t stA = sb + s * STG_BYTES;
        const uint32_t stB = stA + ASTG;
        const __half* agp = g_Ah + (size_t)m0 * NN + ch * KCH;
        const __half* bgp = Bsrc + (size_t)n0 * NN + ch * KCH;
#pragma unroll
        for (int i = 0; i < 8; i++) {
            int idx = t + i * 128;
            int r = idx >> 3, c = idx & 7;
            uint32_t so = SWZ((uint32_t)(r * 128 + c * 16));
            CP_ASYNC16(stA + so, agp + (size_t)r * NN + c * 8);
            CP_ASYNC16(stB + so, bgp + (size_t)r * NN + c * 8);
        }
        CP_COMMIT();
    };

    load_chunk(0, 0);
    load_chunk(1, 1);

    const int a_row  = (lane & 15);
    const int a_kofs = (lane >> 4) << 4;
    const int b_row  = ((lane >> 4) << 3) + (lane & 7);
    const int b_kofs = ((lane >> 3) & 1) << 4;

    for (int ch = 0; ch < NCH; ch++) {
        const int s = ch % STAGES;
        if (ch >= NCH - 2) { CP_WAIT0(); } else { CP_WAIT1(); }
        __syncthreads();
        if (ch + 2 < NCH) load_chunk(ch + 2, (ch + 2) % STAGES);

        const uint32_t stA = sb + s * STG_BYTES;
        const uint32_t stB = stA + ASTG;
#pragma unroll
        for (int kk = 0; kk < 4; kk++) {
            uint32_t a[4][4], b[4][4];
#pragma unroll
            for (int mf = 0; mf < 4; mf++) {
                int r = wm * 64 + mf * 16 + a_row;
                ldsm4(a[mf], stA + SWZ((uint32_t)(r * 128 + kk * 32 + a_kofs)));
            }
#pragma unroll
            for (int nf2 = 0; nf2 < 4; nf2++) {
                int r = wn * 64 + nf2 * 16 + b_row;
                ldsm4(b[nf2], stB + SWZ((uint32_t)(r * 128 + kk * 32 + b_kofs)));
            }
#pragma unroll
            for (int mf = 0; mf < 4; mf++)
#pragma unroll
                for (int nf = 0; nf < 8; nf++)
                    mma16816(acc[mf][nf], a[mf], &b[nf >> 1][(nf & 1) * 2]);
        }
    }
    __syncthreads();

    // ---- epilogue: stage accumulators through smem (fp32) ----
    float* esm = (float*)sal;
#pragma unroll
    for (int mf = 0; mf < 4; mf++) {
#pragma unroll
        for (int nf = 0; nf < 8; nf++) {
            int r = wm * 64 + mf * 16 + (lane >> 2);
            int c = wn * 64 + nf * 8 + (lane & 3) * 2;
            esm[r * EPI_PITCH + c]           = acc[mf][nf][0];
            esm[r * EPI_PITCH + c + 1]       = acc[mf][nf][1];
            esm[(r + 8) * EPI_PITCH + c]     = acc[mf][nf][2];
            esm[(r + 8) * EPI_PITCH + c + 1] = acc[mf][nf][3];
        }
    }
    __syncthreads();

    const int r = t;               // 0..127
    const int n = m0 + r;
    const float inv = g_inv[n];    // softmax row normalization (folded)
    if (PASS == 0) {
#pragma unroll
        for (int h = 0; h < 2; h++) {   // g_Y1nh fp16 [N,B,C]
            const int b = (n0 >> 6) + h;
            uint4* dst = (uint4*)(g_Y1nh + ((size_t)n * BB + b) * CC);
#pragma unroll
            for (int i = 0; i < 8; i++) {
                float4 v0 = *(float4*)&esm[r * EPI_PITCH + h * 64 + i * 8];
                float4 v1 = *(float4*)&esm[r * EPI_PITCH + h * 64 + i * 8 + 4];
                __half2 a0 = __floats2half2_rn(v0.x * inv, v0.y * inv);
                __half2 a1 = __floats2half2_rn(v0.z * inv, v0.w * inv);
                __half2 a2 = __floats2half2_rn(v1.x * inv, v1.y * inv);
                __half2 a3 = __floats2half2_rn(v1.z * inv, v1.w * inv);
                dst[i] = make_uint4(*(uint32_t*)&a0, *(uint32_t*)&a1,
                                    *(uint32_t*)&a2, *(uint32_t*)&a3);
            }
        }
        {   // g_Y1Th fp16 [bc][m]
            const int j = r;
            uint4* d4 = (uint4*)(g_Y1Th + (size_t)(n0 + j) * NN + m0);
#pragma unroll
            for (int q = 0; q < 16; q++) {
                uint32_t p[4];
#pragma unroll
                for (int u = 0; u < 4; u++) {
                    int rr = q * 8 + u * 2;
                    __half2 hv = __floats2half2_rn(
                        esm[rr * EPI_PITCH + j]       * g_inv[m0 + rr],
                        esm[(rr + 1) * EPI_PITCH + j] * g_inv[m0 + rr + 1]);
                    p[u] = *(uint32_t*)&hv;
                }
                d4[q] = make_uint4(p[0], p[1], p[2], p[3]);
            }
        }
    } else {
#pragma unroll
        for (int h = 0; h < 2; h++) {
            const int b = (n0 >> 6) + h;
            const float4* fsrc = (const float4*)(feat + ((size_t)b * NN + n) * CC);
            uint4* dst = (uint4*)(g_Y2nh + ((size_t)n * BB + b) * CC);
            const float s2 = 2.f * inv;
#pragma unroll
            for (int i = 0; i < 8; i++) {
                float4 v0 = *(float4*)&esm[r * EPI_PITCH + h * 64 + i * 8];
                float4 v1 = *(float4*)&esm[r * EPI_PITCH + h * 64 + i * 8 + 4];
                float4 f0 = fsrc[i * 2], f1 = fsrc[i * 2 + 1];
                __half2 a0 = __floats2half2_rn(s2 * v0.x - f0.x, s2 * v0.y - f0.y);
                __half2 a1 = __floats2half2_rn(s2 * v0.z - f0.z, s2 * v0.w - f0.w);
                __half2 a2 = __floats2half2_rn(s2 * v1.x - f1.x, s2 * v1.y - f1.y);
                __half2 a3 = __floats2half2_rn(s2 * v1.z - f1.z, s2 * v1.w - f1.w);
                dst[i] = make_uint4(*(uint32_t*)&a0, *(uint32_t*)&a1,
                                    *(uint32_t*)&a2, *(uint32_t*)&a3);
            }
        }
        __syncthreads();
        if (t == 0) {
            __threadfence();
            atomicAdd(&g_stripe_cnt[(unsigned)m0 >> 7], 1);
        }
    }
}

// ---------------------------------------------------------------------------
extern "C" void kernel_launch(void* const* d_in, const int* in_sizes, int n_in,
                              void* d_out, int out_size)
{
    const float* E     = (const float*)d_in[0];  // [2048,16]
    const float* feat  = (const float*)d_in[1];  // [64,2048,64]
    const float* Wp    = (const float*)d_in[2];  // [16,3,64,64]
    const float* biasP = (const float*)d_in[3];  // [16,64]
    float* out = (float*)d_out;                  // [64,2048,64]

    cudaFuncSetAttribute(prep_kernel, cudaFuncAttributeMaxDynamicSharedMemorySize, PREP_SMEM);
    cudaFuncSetAttribute(gemm_mma<0>, cudaFuncAttributeMaxDynamicSharedMemorySize, GEMM_SMEM);
    cudaFuncSetAttribute(gemm_mma<1>, cudaFuncAttributeMaxDynamicSharedMemorySize, GEMM_SMEM);

    prep_kernel<<<256 + 2048, 256, PREP_SMEM>>>(E, feat);
    gemm_mma<0><<<GEMM_CTAS + CW_CTAS, 128, GEMM_SMEM>>>(feat, E, Wp, biasP, out);
    gemm_mma<1><<<GEMM_CTAS + NN, 128, GEMM_SMEM>>>(feat, E, Wp, biasP, out);
}

// round 16
// speedup vs baseline: 1.0918x; 1.0392x over previous
#include <cuda_runtime.h>
#include <cuda_fp16.h>
#include <cstdint>

// Problem constants
#define NN 2048      // nodes
#define DD 16        // embedding dim
#define BB 64        // batch
#define CC 64        // in channels
#define OO 64        // out channels
#define KK 3         // cheb order
#define KC (KK*CC)   // 192
#define WCOLS (KC*OO) // 12288
#define BC (BB*CC)   // 4096 columns of the big GEMM

// ---------------- scratch (static device allocations allowed) ----------------
__device__ __half g_Ah  [(size_t)NN * NN];      // 8 MB : exp(relu(sim)-max) fp16 (UNNORMALIZED)
__device__ float  g_inv [NN];                   // per-row 1/sum for softmax
__device__ __half g_Fnh [(size_t)NN * BB * CC]; // 16 MB: feat fp16 [N,B,C] (= [m][bc])
__device__ __half g_Y1nh[(size_t)NN * BB * CC]; // 16 MB: Y1  fp16 [N,B,C]
__device__ __half g_Y2nh[(size_t)NN * BB * CC]; // 16 MB: Y2  fp16 [N,B,C]
__device__ __half g_Wh  [(size_t)NN * WCOLS];   // 50 MB: per-node weights fp16
__device__ int    g_stripe_cnt[16];             // gemm<1> m-stripe completion

// ---------------- PTX helpers (baseline ISA only) ----------------
__device__ __forceinline__ uint32_t smem_u32(const void* p) {
    uint32_t a;
    asm("{ .reg .u64 t; cvta.to.shared.u64 t, %1; cvt.u32.u64 %0, t; }" : "=r"(a) : "l"(p));
    return a;
}
#define CP_ASYNC16(dst, src) \
    asm volatile("cp.async.cg.shared.global [%0], [%1], 16;" :: "r"(dst), "l"(src))
#define CP_COMMIT() asm volatile("cp.async.commit_group;" ::: "memory")
#define CP_WAIT2()  asm volatile("cp.async.wait_group 2;" ::: "memory")
#define CP_WAIT1()  asm volatile("cp.async.wait_group 1;" ::: "memory")
#define CP_WAIT0()  asm volatile("cp.async.wait_group 0;" ::: "memory")

__device__ __forceinline__ void ldsm4(uint32_t* r, uint32_t addr) {
    asm volatile("ldmatrix.sync.aligned.m8n8.x4.shared.b16 {%0,%1,%2,%3}, [%4];"
        : "=r"(r[0]), "=r"(r[1]), "=r"(r[2]), "=r"(r[3]) : "r"(addr));
}
__device__ __forceinline__ void ldsm4t(uint32_t* r, uint32_t addr) {
    asm volatile("ldmatrix.sync.aligned.m8n8.x4.trans.shared.b16 {%0,%1,%2,%3}, [%4];"
        : "=r"(r[0]), "=r"(r[1]), "=r"(r[2]), "=r"(r[3]) : "r"(addr));
}
__device__ __forceinline__ void mma16816(float* d, const uint32_t* a, const uint32_t* b) {
    asm volatile("mma.sync.aligned.m16n8k16.row.col.f32.f16.f16.f32 "
        "{%0,%1,%2,%3}, {%4,%5,%6,%7}, {%8,%9}, {%0,%1,%2,%3};"
        : "+f"(d[0]), "+f"(d[1]), "+f"(d[2]), "+f"(d[3])
        : "r"(a[0]), "r"(a[1]), "r"(a[2]), "r"(a[3]), "r"(b[0]), "r"(b[1]));
}
#define SWZ(o) ((o) ^ (((o) >> 3) & 0x70))

// ---------------------------------------------------------------------------
// Kernel 1 (fused prep): blocks [0,256)  -> adjacency exp (8 rows per block)
//                        blocks [256, 2304) -> feat fp16 convert to [N,B,C]
// Adjacency: SINGLE pass of dot products into a smem row buffer; E-tile held
// TRANSPOSED [d][m] pitch 258 (conflict-free). Stores UNNORMALIZED
// exp(s - rowmax) fp16 + g_inv[n]; GEMM epilogue applies inv.
// ---------------------------------------------------------------------------
#define ADJ_TILE 256
#define ET_PITCH 258
#define ET_BYTES (DD * ET_PITCH * 4)          // 16512
#define PREP_SMEM (ET_BYTES + 8 * NN * 4)     // 16512 + 65536 = 82048

__global__ void __launch_bounds__(256) prep_kernel(
    const float* __restrict__ E, const float* __restrict__ feat)
{
    extern __shared__ char praw[];
    const int t = threadIdx.x;

    if (blockIdx.x < 256) {
        if (blockIdx.x == 0 && t < 16) g_stripe_cnt[t] = 0;

        float* etile = (float*)praw;                 // [16][258] transposed
        float* rows  = (float*)(praw + ET_BYTES);    // [8][2048]
        const int lane = t & 31;
        const int w    = t >> 5;
        const int n    = blockIdx.x * 8 + w;

        float e[DD];
#pragma unroll
        for (int d = 0; d < DD; d++) e[d] = E[n * DD + d];

        float* myrow = rows + w * NN;

        // ---- single pass: dots into row buffer ----
        for (int mt = 0; mt < NN / ADJ_TILE; mt++) {
#pragma unroll
            for (int i = 0; i < 4; i++) {            // transposed tile load
                int idx = t + i * 256;               // 0..1023 float4s
                int r   = idx >> 2;
                int c4  = (idx & 3) * 4;
                float4 v = *(const float4*)(E + (size_t)(mt * ADJ_TILE + r) * DD + c4);
                etile[(c4 + 0) * ET_PITCH + r] = v.x;
                etile[(c4 + 1) * ET_PITCH + r] = v.y;
                etile[(c4 + 2) * ET_PITCH + r] = v.z;
                etile[(c4 + 3) * ET_PITCH + r] = v.w;
            }
            __syncthreads();
#pragma unroll 2
            for (int j = 0; j < ADJ_TILE / 32; j++) {
                int mm = j * 32 + lane;
                float s = 0.f;
#pragma unroll
                for (int d = 0; d < DD; d++) s += e[d] * etile[d * ET_PITCH + mm];
                myrow[mt * ADJ_TILE + mm] = s;       // raw s (relu folded into max)
            }
            __syncthreads();
        }

        // ---- row max (relu implied: lmax starts at 0) ----
        float lmax = 0.0f;
#pragma unroll 4
        for (int m = lane; m < NN; m += 32) lmax = fmaxf(lmax, myrow[m]);
#pragma unroll
        for (int off = 16; off > 0; off >>= 1)
            lmax = fmaxf(lmax, __shfl_xor_sync(0xffffffffu, lmax, off));

        // ---- exp + sum + store unnormalized fp16 ----
        float lsum = 0.f;
#pragma unroll 4
        for (int m = lane; m < NN; m += 32) {
            float v = expf(fmaxf(myrow[m], 0.0f) - lmax);
            lsum += v;
            g_Ah[(size_t)n * NN + m] = __float2half(v);
        }
#pragma unroll
        for (int off = 16; off > 0; off >>= 1)
            lsum += __shfl_xor_sync(0xffffffffu, lsum, off);
        if (lane == 0) g_inv[n] = 1.0f / lsum;
    } else {
        // ----- feat fp16 convert: feat[b][m][c] -> g_Fnh[m][b][c]  (no smem) -----
        const int bid2 = blockIdx.x - 256;
        const int m0 = (bid2 & 31) * 64;
        const int b  = bid2 >> 5;

        const int mr = t >> 4, c4 = (t & 15) * 4;
#pragma unroll
        for (int p = 0; p < 4; p++) {
            const int m = m0 + mr + p * 16;
            float4 v = *(const float4*)(feat + ((size_t)b * NN + m) * CC + c4);
            __half2 h0 = __floats2half2_rn(v.x, v.y);
            __half2 h1 = __floats2half2_rn(v.z, v.w);
            *(uint2*)(g_Fnh + ((size_t)m * BB + b) * CC + c4) =
                make_uint2(*(uint32_t*)&h0, *(uint32_t*)&h1);
        }
    }
}

// ---------------------------------------------------------------------------
// compute_weights as a 128-thread device block (folded into gemm<0> launch)
// ---------------------------------------------------------------------------
__device__ void cw_block(char* smem, const float* __restrict__ E,
                         const float* __restrict__ Wp, int cwid)
{
    const int col0 = (cwid % 96) * 128;
    const int n0   = (cwid / 96) * 64;
    const int t    = threadIdx.x;   // 0..127

    float* ws = (float*)smem;        // [16][128]
    float* es = ws + DD * 128;       // [64][16]

#pragma unroll
    for (int i = 0; i < 4; i++) {
        int idx = t + i * 128;
        int r = idx >> 5;
        int c = (idx & 31) * 4;
        *(float4*)&ws[r * 128 + c] = *(const float4*)(Wp + (size_t)r * WCOLS + col0 + c);
    }
#pragma unroll
    for (int i = 0; i < 2; i++) {
        int idx = t + i * 128;
        int r = idx >> 2;
        int c = (idx & 3) * 4;
        *(float4*)&es[r * DD + c] = *(const float4*)(E + (n0 + r) * DD + c);
    }
    __syncthreads();

    const int tx = t & 31;
    const int ty = t >> 5;
#pragma unroll
    for (int nn = ty; nn < 64; nn += 4) {
        float4 acc = make_float4(0.f, 0.f, 0.f, 0.f);
#pragma unroll
        for (int d = 0; d < DD; d++) {
            float ev = es[nn * DD + d];
            float4 w = *(const float4*)&ws[d * 128 + tx * 4];
            acc.x += ev * w.x; acc.y += ev * w.y;
            acc.z += ev * w.z; acc.w += ev * w.w;
        }
        __half2 h0 = __floats2half2_rn(acc.x, acc.y);
        __half2 h1 = __floats2half2_rn(acc.z, acc.w);
        *(uint2*)(g_Wh + (size_t)(n0 + nn) * WCOLS + col0 + tx * 4) =
            make_uint2(*(uint32_t*)&h0, *(uint32_t*)&h1);
    }
}

// ---------------------------------------------------------------------------
// final_gconv as a 128-thread device block (folded into gemm<1> launch).
// Waits on gemm1 m-stripe for its node (cw completed in launch 2).
// ---------------------------------------------------------------------------
#define FG_A_OFF   0       // 3 * 8192 = 24576
#define FG_B_OFF   24576   // 192 * 128 = 24576
#define FG_BIAS    49152   // 64 floats
#define FG_OPITCH  68

__device__ void final_block(char* sal, uint32_t sb, int n,
                            const float* __restrict__ E,
                            const float* __restrict__ biasP,
                            float* __restrict__ out)
{
    const int t    = threadIdx.x;   // 0..127
    const int lane = t & 31;
    const int wid  = t >> 5;
    const int wm   = wid >> 1;      // 0..1 : b rows wm*32
    const int wn   = wid & 1;       // 0..1 : o cols wn*32

    if (t == 0) {
        while (atomicAdd(&g_stripe_cnt[n >> 7], 0) < 32) __nanosleep(64);
        __threadfence();
    }
    __syncthreads();

    const char* asrc[KK] = {
        (const char*)(g_Fnh  + (size_t)n * (BB * CC)),
        (const char*)(g_Y1nh + (size_t)n * (BB * CC)),
        (const char*)(g_Y2nh + (size_t)n * (BB * CC)) };
    const char* wsrc = (const char*)(g_Wh + (size_t)n * WCOLS);
#pragma unroll
    for (int p = 0; p < 3; p++) {
#pragma unroll
        for (int i = 0; i < 4; i++) {
            int idx = t + i * 128;
            uint32_t so = SWZ((uint32_t)(idx * 16));
            CP_ASYNC16(sb + FG_A_OFF + p * 8192 + so, asrc[p] + idx * 16);
        }
#pragma unroll
        for (int i = 0; i < 4; i++) {
            int idx = p * 512 + t + i * 128;
            uint32_t so = SWZ((uint32_t)(idx * 16));
            CP_ASYNC16(sb + FG_B_OFF + so, wsrc + (size_t)idx * 16);
        }
        CP_COMMIT();
    }

    float* bias_s = (float*)(sal + FG_BIAS);
    if (t < OO) {
        float s = 0.f;
#pragma unroll
        for (int d = 0; d < DD; d++) s += E[n * DD + d] * biasP[d * OO + t];
        bias_s[t] = s;
    }

    float acc[2][4][4];
#pragma unroll
    for (int mf = 0; mf < 2; mf++)
#pragma unroll
        for (int nf = 0; nf < 4; nf++)
#pragma unroll
            for (int q = 0; q < 4; q++) acc[mf][nf][q] = 0.f;

    const int a_row  = lane & 15;
    const int a_kofs = (lane >> 4) << 4;
    const int bt_row = lane & 15;
    const int bt_col = (lane >> 4) << 3;

#pragma unroll
    for (int p = 0; p < 3; p++) {
        if (p == 0) { CP_WAIT2(); } else if (p == 1) { CP_WAIT1(); } else { CP_WAIT0(); }
        __syncthreads();
#pragma unroll
        for (int kko = 0; kko < 4; kko++) {
            const int kk = p * 4 + kko;
            uint32_t a[2][4], b[2][4];
#pragma unroll
            for (int mf = 0; mf < 2; mf++)
                ldsm4(a[mf], sb + FG_A_OFF + p * 8192 +
                      SWZ((uint32_t)((wm * 32 + mf * 16 + a_row) * 128 + kko * 32 + a_kofs)));
#pragma unroll
            for (int j = 0; j < 2; j++)
                ldsm4t(b[j], sb + FG_B_OFF +
                       SWZ((uint32_t)((kk * 16 + bt_row) * 128 + (wn * 32 + j * 16 + bt_col) * 2)));
#pragma unroll
            for (int mf = 0; mf < 2; mf++)
#pragma unroll
                for (int j = 0; j < 2; j++) {
                    mma16816(acc[mf][j * 2 + 0], a[mf], &b[j][0]);
                    mma16816(acc[mf][j * 2 + 1], a[mf], &b[j][2]);
                }
        }
    }
    __syncthreads();

    float* osm = (float*)sal;
#pragma unroll
    for (int mf = 0; mf < 2; mf++)
#pragma unroll
        for (int nf = 0; nf < 4; nf++) {
            int r = wm * 32 + mf * 16 + (lane >> 2);
            int c = wn * 32 + nf * 8 + (lane & 3) * 2;
            osm[r * FG_OPITCH + c]           = acc[mf][nf][0];
            osm[r * FG_OPITCH + c + 1]       = acc[mf][nf][1];
            osm[(r + 8) * FG_OPITCH + c]     = acc[mf][nf][2];
            osm[(r + 8) * FG_OPITCH + c + 1] = acc[mf][nf][3];
        }
    __syncthreads();

    const int b  = t >> 1;
    const int q0 = (t & 1) * 32;
    float* dst = out + ((size_t)b * NN + n) * OO + q0;
#pragma unroll
    for (int i = 0; i < 8; i++) {
        float4 v = *(float4*)&osm[b * FG_OPITCH + q0 + i * 4];
        v.x += bias_s[q0 + i * 4 + 0];
        v.y += bias_s[q0 + i * 4 + 1];
        v.z += bias_s[q0 + i * 4 + 2];
        v.w += bias_s[q0 + i * 4 + 3];
        *(float4*)(dst + i * 4) = v;
    }
}

// ---------------------------------------------------------------------------
// Kernel 2: mma.sync fp16 GEMM.  D[n, bc] = inv[n] * sum_m Ah[n,m] * B[m, bc]
// B read DIRECTLY from node-major [m][bc] tensors via ldmatrix.trans
// (two 64x64 SW128 subtiles per B stage; warp wn reads subtile wn).
//   PASS 0: B = g_Fnh ; writes g_Y1nh.  bid >= 512 -> cw_block.
//   PASS 1: B = g_Y1nh; writes g_Y2nh; stripe counters; bid >= 512 -> final.
// ---------------------------------------------------------------------------
#define MT 128
#define NT 128
#define KCH 64
#define NCH (NN / KCH)     // 32
#define ASTG (MT * 128)    // 16 KB
#define BSTG (NT * 128)    // 16 KB (2 x 8 KB subtiles)
#define STG_BYTES (ASTG + BSTG)
#define STAGES 3
#define EPI_PITCH 132
#define GEMM_SMEM (STAGES * STG_BYTES + 1024)
#define GEMM_CTAS ((NN / MT) * (BC / NT))     // 512
#define CW_CTAS   ((WCOLS / 128) * (NN / 64)) // 3072

template <int PASS>
__global__ void __launch_bounds__(128, 2) gemm_mma(
    const float* __restrict__ feat,
    const float* __restrict__ E,
    const float* __restrict__ Wp,
    const float* __restrict__ biasP,
    float* __restrict__ out)
{
    extern __shared__ char smem_raw[];
    char* sal = (char*)(((uintptr_t)smem_raw + 1023) & ~(uintptr_t)1023);
    const uint32_t sb = smem_u32(sal);

    if (PASS == 0 && blockIdx.x >= GEMM_CTAS) {
        cw_block(smem_raw, E, Wp, blockIdx.x - GEMM_CTAS);
        return;
    }
    if (PASS == 1 && blockIdx.x >= GEMM_CTAS) {
        final_block(sal, sb, blockIdx.x - GEMM_CTAS, E, biasP, out);
        return;
    }

    const int t    = threadIdx.x;
    const int lane = t & 31;
    const int wid  = t >> 5;
    const int wm   = wid >> 1;
    const int wn   = wid & 1;
    const int m0   = PASS ? (blockIdx.x >> 5) * MT : (blockIdx.x & 15) * MT;
    const int n0   = PASS ? (blockIdx.x & 31) * NT : (blockIdx.x >> 4) * NT;

    const __half* __restrict__ Bsrc = PASS ? g_Y1nh : g_Fnh;   // [m][bc]

    float acc[4][8][4];
#pragma unroll
    for (int i = 0; i < 4; i++)
#pragma unroll
        for (int j = 0; j < 8; j++)
#pragma unroll
            for (int q = 0; q < 4; q++) acc[i][j][q] = 0.f;

    auto load_chunk = [&](int ch, int s) {
        const uint32_t stA = sb + s * STG_BYTES;
        const uint32_t stB = stA + ASTG;
        const __half* agp = g_Ah + (size_t)m0 * NN + ch * KCH;
        const __half* bgp = Bsrc + (size_t)(ch * KCH) * BC + n0;
#pragma unroll
        for (int i = 0; i < 8; i++) {
            // A: rows n (128), 128B each
            int idx = t + i * 128;            // 0..1023
            int r = idx >> 3, c = idx & 7;
            uint32_t so = SWZ((uint32_t)(r * 128 + c * 16));
            CP_ASYNC16(stA + so, agp + (size_t)r * NN + c * 8);
            // B: rows m (64) x 128 bc, split into 2 subtiles of 64 bc (128B rows)
            int bj = idx >> 9;                // subtile 0/1
            int br = (idx >> 3) & 63;         // m row within chunk
            uint32_t bso = SWZ((uint32_t)(br * 128 + c * 16));
            CP_ASYNC16(stB + bj * 8192 + bso,
                       bgp + (size_t)br * BC + bj * 64 + c * 8);
        }
        CP_COMMIT();
    };

    load_chunk(0, 0);
    load_chunk(1, 1);

    const int a_row  = (lane & 15);
    const int a_kofs = (lane >> 4) << 4;
    const int bt_row = lane & 15;             // k (m) within 16
    const int bt_col = (lane >> 4) << 3;      // n offset within 16

    for (int ch = 0; ch < NCH; ch++) {
        const int s = ch % STAGES;
        if (ch >= NCH - 2) { CP_WAIT0(); } else { CP_WAIT1(); }
        __syncthreads();
        if (ch + 2 < NCH) load_chunk(ch + 2, (ch + 2) % STAGES);

        const uint32_t stA = sb + s * STG_BYTES;
        const uint32_t stB = stA + ASTG + wn * 8192;   // warp's own subtile
#pragma unroll
        for (int kk = 0; kk < 4; kk++) {
            uint32_t a[4][4], b[4][4];
#pragma unroll
            for (int mf = 0; mf < 4; mf++) {
                int r = wm * 64 + mf * 16 + a_row;
                ldsm4(a[mf], stA + SWZ((uint32_t)(r * 128 + kk * 32 + a_kofs)));
            }
#pragma unroll
            for (int nf2 = 0; nf2 < 4; nf2++)
                ldsm4t(b[nf2], stB + SWZ((uint32_t)((kk * 16 + bt_row) * 128 +
                                                    (nf2 * 16 + bt_col) * 2)));
#pragma unroll
            for (int mf = 0; mf < 4; mf++)
#pragma unroll
                for (int nf = 0; nf < 8; nf++)
                    mma16816(acc[mf][nf], a[mf], &b[nf >> 1][(nf & 1) * 2]);
        }
    }
    __syncthreads();

    // ---- epilogue: stage accumulators through smem (fp32) ----
    float* esm = (float*)sal;
#pragma unroll
    for (int mf = 0; mf < 4; mf++) {
#pragma unroll
        for (int nf = 0; nf < 8; nf++) {
            int r = wm * 64 + mf * 16 + (lane >> 2);
            int c = wn * 64 + nf * 8 + (lane & 3) * 2;
            esm[r * EPI_PITCH + c]           = acc[mf][nf][0];
            esm[r * EPI_PITCH + c + 1]       = acc[mf][nf][1];
            esm[(r + 8) * EPI_PITCH + c]     = acc[mf][nf][2];
            esm[(r + 8) * EPI_PITCH + c + 1] = acc[mf][nf][3];
        }
    }
    __syncthreads();

    const int r = t;               // 0..127
    const int n = m0 + r;
    const float inv = g_inv[n];    // softmax row normalization (folded)
    if (PASS == 0) {
#pragma unroll
        for (int h = 0; h < 2; h++) {   // g_Y1nh fp16 [N,B,C]
            const int b = (n0 >> 6) + h;
            uint4* dst = (uint4*)(g_Y1nh + ((size_t)n * BB + b) * CC);
#pragma unroll
            for (int i = 0; i < 8; i++) {
                float4 v0 = *(float4*)&esm[r * EPI_PITCH + h * 64 + i * 8];
                float4 v1 = *(float4*)&esm[r * EPI_PITCH + h * 64 + i * 8 + 4];
                __half2 a0 = __floats2half2_rn(v0.x * inv, v0.y * inv);
                __half2 a1 = __floats2half2_rn(v0.z * inv, v0.w * inv);
                __half2 a2 = __floats2half2_rn(v1.x * inv, v1.y * inv);
                __half2 a3 = __floats2half2_rn(v1.z * inv, v1.w * inv);
                dst[i] = make_uint4(*(uint32_t*)&a0, *(uint32_t*)&a1,
                                    *(uint32_t*)&a2, *(uint32_t*)&a3);
            }
        }
    } else {
#pragma unroll
        for (int h = 0; h < 2; h++) {
            const int b = (n0 >> 6) + h;
            const float4* fsrc = (const float4*)(feat + ((size_t)b * NN + n) * CC);
            uint4* dst = (uint4*)(g_Y2nh + ((size_t)n * BB + b) * CC);
            const float s2 = 2.f * inv;
#pragma unroll
            for (int i = 0; i < 8; i++) {
                float4 v0 = *(float4*)&esm[r * EPI_PITCH + h * 64 + i * 8];
                float4 v1 = *(float4*)&esm[r * EPI_PITCH + h * 64 + i * 8 + 4];
                float4 f0 = fsrc[i * 2], f1 = fsrc[i * 2 + 1];
                __half2 a0 = __floats2half2_rn(s2 * v0.x - f0.x, s2 * v0.y - f0.y);
                __half2 a1 = __floats2half2_rn(s2 * v0.z - f0.z, s2 * v0.w - f0.w);
                __half2 a2 = __floats2half2_rn(s2 * v1.x - f1.x, s2 * v1.y - f1.y);
                __half2 a3 = __floats2half2_rn(s2 * v1.z - f1.z, s2 * v1.w - f1.w);
                dst[i] = make_uint4(*(uint32_t*)&a0, *(uint32_t*)&a1,
                                    *(uint32_t*)&a2, *(uint32_t*)&a3);
            }
        }
        __syncthreads();
        if (t == 0) {
            __threadfence();
            atomicAdd(&g_stripe_cnt[(unsigned)m0 >> 7], 1);
        }
    }
}

// ---------------------------------------------------------------------------
extern "C" void kernel_launch(void* const* d_in, const int* in_sizes, int n_in,
                              void* d_out, int out_size)
{
    const float* E     = (const float*)d_in[0];  // [2048,16]
    const float* feat  = (const float*)d_in[1];  // [64,2048,64]
    const float* Wp    = (const float*)d_in[2];  // [16,3,64,64]
    const float* biasP = (const float*)d_in[3];  // [16,64]
    float* out = (float*)d_out;                  // [64,2048,64]

    cudaFuncSetAttribute(prep_kernel, cudaFuncAttributeMaxDynamicSharedMemorySize, PREP_SMEM);
    cudaFuncSetAttribute(gemm_mma<0>, cudaFuncAttributeMaxDynamicSharedMemorySize, GEMM_SMEM);
    cudaFuncSetAttribute(gemm_mma<1>, cudaFuncAttributeMaxDynamicSharedMemorySize, GEMM_SMEM);

    prep_kernel<<<256 + 2048, 256, PREP_SMEM>>>(E, feat);
    gemm_mma<0><<<GEMM_CTAS + CW_CTAS, 128, GEMM_SMEM>>>(feat, E, Wp, biasP, out);
    gemm_mma<1><<<GEMM_CTAS + NN, 128, GEMM_SMEM>>>(feat, E, Wp, biasP, out);
}